// round 4
// baseline (speedup 1.0000x reference)
#include <cuda_runtime.h>

// Problem constants
#define BB   32
#define CI   64
#define CO   64
#define HH   128
#define WW   128
#define M1   32
#define M2   32
#define SS   64      // retained kx rows: {0..31} U {96..127}
#define WOUT 65      // rfft width = W/2+1 = ifft length on last axis
#define MPAD 68      // m padded for tiling

typedef unsigned long long u64;
__device__ __forceinline__ u64 pk2(float lo, float hi){ u64 r; asm("mov.b64 %0,{%1,%2};" : "=l"(r) : "f"(lo), "f"(hi)); return r; }
__device__ __forceinline__ u64 bc2(float v){ return pk2(v, v); }
__device__ __forceinline__ void fm2(u64& d, u64 a, u64 b){ asm("fma.rn.f32x2 %0,%1,%2,%0;" : "+l"(d) : "l"(a), "l"(b)); }
__device__ __forceinline__ float2 up2(u64 v){ float2 r; asm("mov.b64 {%0,%1},%2;" : "=f"(r.x), "=f"(r.y) : "l"(v)); return r; }
__device__ __forceinline__ u64 ld2(const float* p){ return *(const u64*)p; }

// ---------------- scratch (device globals) ----------------
__device__ float2 g_Y[(size_t)BB * CI * HH * M2];    // stage A out: [bi][n][ky]
__device__ float2 g_X[(size_t)SS * M2 * BB * CI];    // stage B out: [mode][b*64+i]
__device__ float2 g_G[(size_t)SS * M2 * BB * CO];    // stage C out: [mode][b*64+o]
__device__ float2 g_T[(size_t)BB * CO * SS * MPAD];  // stage D out: [bo][s][m]
__device__ float2 g_W[(size_t)SS * M2 * CI * CO];    // transposed weights: [mode][i][o]

// twiddle tables
__device__ float2 g_FA[M2 * M2];     // [n1][ky]  e^{-2pi i ky n1/128}
__device__ float2 g_FB[SS * 32];     // [s][n1]   e^{-2pi i kx(s) n1/128}
__device__ float2 g_E2[SS * 32];     // [s][n1]   e^{+2pi i kx(s) n1/128}
__device__ float2 g_IKY[M2 * MPAD];  // [ky][m]   e^{+2pi i ky m/65}

// ---------------- twiddle fill ----------------
__global__ void k_fill() {
    int t  = blockIdx.x * blockDim.x + threadIdx.x;
    int NT = gridDim.x * blockDim.x;
    const double P2 = 6.283185307179586476925286766559;

    for (int idx = t; idx < M2 * M2; idx += NT) {
        int n1 = idx >> 5, ky = idx & 31;
        double a = -P2 * (double)((ky * n1) & 127) / 128.0;
        g_FA[idx] = make_float2((float)cos(a), (float)sin(a));
    }
    for (int idx = t; idx < SS * 32; idx += NT) {
        int s = idx >> 5, n1 = idx & 31;
        int kx = (s < 32) ? s : (s + 64);
        double a = -P2 * (double)((kx * n1) & 127) / 128.0;
        float c = (float)cos(a), sn = (float)sin(a);
        g_FB[idx] = make_float2(c, sn);
        g_E2[idx] = make_float2(c, -sn);
    }
    for (int idx = t; idx < M2 * MPAD; idx += NT) {
        int ky = idx / MPAD, m = idx % MPAD;
        double a = P2 * (double)((ky * m) % 65) / 65.0;
        g_IKY[idx] = make_float2((float)cos(a), (float)sin(a));
    }
}

// ---------------- kW: weight transpose -> g_W[mode][i][o] ----------------
__global__ __launch_bounds__(256) void kW(const float* __restrict__ w1r, const float* __restrict__ w1i,
                                          const float* __restrict__ w2r, const float* __restrict__ w2i) {
    __shared__ float2 tile[CO][33];
    int tid = threadIdx.x;
    int s = blockIdx.x >> 6, i = blockIdx.x & 63;
    const float* wr = (s < 32) ? w1r : w2r;
    const float* wi = (s < 32) ? w1i : w2i;
    int sm = s & 31;

    for (int idx = tid; idx < CO * M2; idx += 256) {
        int o = idx >> 5, ky = idx & 31;
        size_t g = ((size_t)(i * CO + o) * M1 + sm) * M2 + ky;
        tile[o][ky] = make_float2(wr[g], wi[g]);
    }
    __syncthreads();
    for (int idx = tid; idx < M2 * CO; idx += 256) {
        int ky = idx >> 6, o = idx & 63;
        g_W[((size_t)(s * 32 + ky) * CI + i) * CO + o] = tile[o][ky];
    }
}

// ---------------- Stage A: real DFT along W (128 -> 32), radix-4 + FFMA2 ----------------
// Block: 32 rows, 128 threads. ky = tid&31, rg = tid>>5; thread rows rg*8..rg*8+7 (4 pairs).
__global__ __launch_bounds__(128) void kA(const float* __restrict__ x) {
    __shared__ float ysr[4][32][34];   // [cls][n1][row], SoA real
    __shared__ float ysi[4][32][34];   // imag
    __shared__ float2 tws[32][32];     // [n1][ky]
    int tid = threadIdx.x;

    for (int idx = tid; idx < 1024; idx += 128)
        ((float2*)tws)[idx] = g_FA[idx];

    size_t rowBase = (size_t)blockIdx.x * 32;
#pragma unroll
    for (int it = 0; it < 8; it++) {
        int idx = tid + 128 * it;
        int row = idx >> 5, n1 = idx & 31;
        const float* xp = x + (rowBase + row) * WW;
        float x0 = xp[n1], x1 = xp[n1 + 32], x2 = xp[n1 + 64], x3 = xp[n1 + 96];
        float p = x0 + x2, q = x0 - x2, u = x1 + x3, v = x3 - x1;
        ysr[0][n1][row] = p + u; ysi[0][n1][row] = 0.f;
        ysr[2][n1][row] = p - u; ysi[2][n1][row] = 0.f;
        ysr[1][n1][row] = q;     ysi[1][n1][row] = v;
        ysr[3][n1][row] = q;     ysi[3][n1][row] = -v;
    }
    __syncthreads();

    int ky = tid & 31, rg = tid >> 5, cls = ky & 3;
    u64 aX[4], aY[4];
#pragma unroll
    for (int p = 0; p < 4; p++) { aX[p] = 0ull; aY[p] = 0ull; }

    for (int n1 = 0; n1 < 32; n1++) {
        float2 tw = tws[n1][ky];
        u64 txx = bc2(tw.x), tyy = bc2(tw.y), ntyy = bc2(-tw.y);
        const float* br = &ysr[cls][n1][rg * 8];
        const float* bi = &ysi[cls][n1][rg * 8];
#pragma unroll
        for (int p = 0; p < 4; p++) {
            u64 yr = ld2(br + 2 * p), yi = ld2(bi + 2 * p);
            fm2(aX[p], yr, txx); fm2(aX[p], yi, ntyy);
            fm2(aY[p], yr, tyy); fm2(aY[p], yi, txx);
        }
    }
#pragma unroll
    for (int p = 0; p < 4; p++) {
        float2 X = up2(aX[p]), Y = up2(aY[p]);
        size_t r0 = rowBase + rg * 8 + 2 * p;
        g_Y[r0 * M2 + ky]       = make_float2(X.x, Y.x);
        g_Y[(r0 + 1) * M2 + ky] = make_float2(X.y, Y.y);
    }
}

// ---------------- Stage B: complex DFT along H (128 -> 64), radix-4 + FFMA2 ----------------
// Block per bi, 256 threads. Warp sg: cls = sg&3, thalf = sg>>2.
// s = cls + 4*t, t = thalf*8 + {0..7} (4 adjacent t-pairs). tw SoA [n1][cls*16+t].
__global__ __launch_bounds__(256, 4) void kB() {
    __shared__ float2 ys[4][32][32];   // [cls][n1][ky] 32 KB
    __shared__ float twr[32][66];      // [n1][cls*16+t]
    __shared__ float twi[32][66];
    int tid = threadIdx.x;
    int bi  = blockIdx.x;
    const float2* Yg = g_Y + (size_t)bi * HH * M2;

    for (int idx = tid; idx < SS * 32; idx += 256) {
        int s = idx >> 5, n1 = idx & 31;
        float2 t = g_FB[idx];
        int col = (s & 3) * 16 + (s >> 2);
        twr[n1][col] = t.x; twi[n1][col] = t.y;
    }
#pragma unroll
    for (int it = 0; it < 4; it++) {
        int idx = tid + 256 * it;
        int n1 = idx >> 5, ky = idx & 31;
        float2 Y0 = Yg[n1 * 32 + ky];
        float2 Y1 = Yg[(n1 + 32) * 32 + ky];
        float2 Y2 = Yg[(n1 + 64) * 32 + ky];
        float2 Y3 = Yg[(n1 + 96) * 32 + ky];
        float2 a = make_float2(Y0.x + Y2.x, Y0.y + Y2.y);
        float2 b = make_float2(Y0.x - Y2.x, Y0.y - Y2.y);
        float2 c = make_float2(Y1.x + Y3.x, Y1.y + Y3.y);
        float2 d = make_float2(Y1.x - Y3.x, Y1.y - Y3.y);
        ys[0][n1][ky] = make_float2(a.x + c.x, a.y + c.y);
        ys[2][n1][ky] = make_float2(a.x - c.x, a.y - c.y);
        ys[1][n1][ky] = make_float2(b.x + d.y, b.y - d.x);
        ys[3][n1][ky] = make_float2(b.x - d.y, b.y + d.x);
    }
    __syncthreads();

    int ky = tid & 31, sg = tid >> 5;
    int cls = sg & 3, tbase = (sg >> 2) * 8;
    int col0 = cls * 16 + tbase;
    u64 aX[4], aY[4];
#pragma unroll
    for (int p = 0; p < 4; p++) { aX[p] = 0ull; aY[p] = 0ull; }

    for (int n1 = 0; n1 < 32; n1++) {
        float2 y = ys[cls][n1][ky];
        u64 yxx = bc2(y.x), yyy = bc2(y.y), nyy = bc2(-y.y);
        const float* tr = &twr[n1][col0];
        const float* ti = &twi[n1][col0];
#pragma unroll
        for (int p = 0; p < 4; p++) {
            u64 tx = ld2(tr + 2 * p), ty = ld2(ti + 2 * p);
            // X += yx*tx - yy*ty ; Y += yx*ty + yy*tx
            fm2(aX[p], yxx, tx); fm2(aX[p], nyy, ty);
            fm2(aY[p], yxx, ty); fm2(aY[p], yyy, tx);
        }
    }
#pragma unroll
    for (int p = 0; p < 4; p++) {
        float2 X = up2(aX[p]), Y = up2(aY[p]);
        int t0 = tbase + 2 * p;
        int s0 = cls + 4 * t0, s1 = s0 + 4;
        g_X[((size_t)(s0 * 32 + ky)) * (BB * CI) + bi] = make_float2(X.x, Y.x);
        g_X[((size_t)(s1 * 32 + ky)) * (BB * CI) + bi] = make_float2(X.y, Y.y);
    }
}

// ---------------- Stage C: per-mode channel mix G = X * conj(W), FFMA2 ----------------
// Block per mode, 128 threads: o = tid&31 (covers o, o+32), bg = tid>>5; b = bg*8..bg*8+7.
__global__ __launch_bounds__(128, 6) void kC() {
    __shared__ float Xr[32][34];    // [il][b] SoA
    __shared__ float Xi[32][34];
    __shared__ float2 Ws[32][CO];   // [il][o]
    int tid  = threadIdx.x;
    int mode = blockIdx.x;

    const float2* Xg = g_X + (size_t)mode * (BB * CI);
    const float2* Wg = g_W + (size_t)mode * (CI * CO);

    int o = tid & 31, bg = tid >> 5;
    u64 aX0[4], aY0[4], aX1[4], aY1[4];
#pragma unroll
    for (int p = 0; p < 4; p++) { aX0[p] = aY0[p] = aX1[p] = aY1[p] = 0ull; }

    for (int c = 0; c < 2; c++) {
        __syncthreads();
        for (int idx = tid; idx < BB * 32; idx += 128) {
            int b = idx >> 5, il = idx & 31;
            float2 v = Xg[b * CI + c * 32 + il];
            Xr[il][b] = v.x; Xi[il][b] = v.y;
        }
        for (int idx = tid; idx < 32 * CO; idx += 128)
            ((float2*)Ws)[idx] = Wg[c * 32 * CO + idx];
        __syncthreads();

        for (int il = 0; il < 32; il++) {
            float2 w0 = Ws[il][o];
            float2 w1 = Ws[il][o + 32];
            u64 w0rr = bc2(w0.x), w0ii = bc2(w0.y), nw0ii = bc2(-w0.y);
            u64 w1rr = bc2(w1.x), w1ii = bc2(w1.y), nw1ii = bc2(-w1.y);
            const float* xr = &Xr[il][bg * 8];
            const float* xi = &Xi[il][bg * 8];
#pragma unroll
            for (int p = 0; p < 4; p++) {
                u64 xr01 = ld2(xr + 2 * p), xi01 = ld2(xi + 2 * p);
                // X += xr*wr + xi*wi ; Y += xi*wr - xr*wi
                fm2(aX0[p], xr01, w0rr); fm2(aX0[p], xi01, w0ii);
                fm2(aY0[p], xi01, w0rr); fm2(aY0[p], xr01, nw0ii);
                fm2(aX1[p], xr01, w1rr); fm2(aX1[p], xi01, w1ii);
                fm2(aY1[p], xi01, w1rr); fm2(aY1[p], xr01, nw1ii);
            }
        }
    }
    float2* Gp = g_G + (size_t)mode * (BB * CO);
#pragma unroll
    for (int p = 0; p < 4; p++) {
        int b0 = bg * 8 + 2 * p;
        float2 X0 = up2(aX0[p]), Y0 = up2(aY0[p]);
        float2 X1 = up2(aX1[p]), Y1 = up2(aY1[p]);
        Gp[b0 * CO + o]            = make_float2(X0.x, Y0.x);
        Gp[(b0 + 1) * CO + o]      = make_float2(X0.y, Y0.y);
        Gp[b0 * CO + o + 32]       = make_float2(X1.x, Y1.x);
        Gp[(b0 + 1) * CO + o + 32] = make_float2(X1.y, Y1.y);
    }
}

// ---------------- Stage D: inverse length-65 DFT along ky (32 -> 68), FFMA2 ----------------
// Block per (s, 32-wide bo chunk). 272 threads: m = tid%68, bg = tid/68; bo_local = bg*8..+7.
__global__ __launch_bounds__(272, 4) void kD() {
    __shared__ float Gr[M2][34];      // [ky][bo_local] SoA
    __shared__ float Gi[M2][34];
    __shared__ float2 Ks[M2][MPAD];
    int tid = threadIdx.x;
    int s  = blockIdx.x >> 6;
    int cb = blockIdx.x & 63;
    int bo0 = cb * 32;

    for (int idx = tid; idx < M2 * 32; idx += 272) {
        int ky = idx >> 5, bol = idx & 31;
        float2 v = g_G[(size_t)(s * 32 + ky) * (BB * CO) + bo0 + bol];
        Gr[ky][bol] = v.x; Gi[ky][bol] = v.y;
    }
    for (int idx = tid; idx < M2 * MPAD; idx += 272)
        ((float2*)Ks)[idx] = g_IKY[idx];
    __syncthreads();

    int m = tid % MPAD, bg = tid / MPAD;
    u64 aX[4], aY[4];
#pragma unroll
    for (int p = 0; p < 4; p++) { aX[p] = 0ull; aY[p] = 0ull; }

    for (int ky = 0; ky < M2; ky++) {
        float2 e = Ks[ky][m];
        u64 exx = bc2(e.x), eyy = bc2(e.y), neyy = bc2(-e.y);
        const float* gr = &Gr[ky][bg * 8];
        const float* gi = &Gi[ky][bg * 8];
#pragma unroll
        for (int p = 0; p < 4; p++) {
            u64 gx = ld2(gr + 2 * p), gy = ld2(gi + 2 * p);
            // X += gx*ex - gy*ey ; Y += gx*ey + gy*ex
            fm2(aX[p], gx, exx); fm2(aX[p], gy, neyy);
            fm2(aY[p], gx, eyy); fm2(aY[p], gy, exx);
        }
    }
#pragma unroll
    for (int p = 0; p < 4; p++) {
        float2 X = up2(aX[p]), Y = up2(aY[p]);
        int b0 = bo0 + bg * 8 + 2 * p;
        g_T[((size_t)b0 * SS + s) * MPAD + m]       = make_float2(X.x, Y.x);
        g_T[((size_t)(b0 + 1) * SS + s) * MPAD + m] = make_float2(X.y, Y.y);
    }
}

// ---------------- Stage E: inverse DFT along kx, radix-4 grouped, FFMA2, real part ----------------
// 544 threads: m = tid%68, ng = tid/68; n1 = ng*4 + {0..3} (2 adjacent pairs).
// Classes r=0,2 need only Re accumulators.
__global__ __launch_bounds__(544, 2) void kE(float* __restrict__ out) {
    __shared__ float2 Ts[32][MPAD];   // 17.4 KB
    __shared__ float Er[SS][32];      // [s][n1] SoA
    __shared__ float Ei[SS][32];
    int tid = threadIdx.x;
    int bo  = blockIdx.x;
    int m = tid % MPAD, ng = tid / MPAD;

    for (int idx = tid; idx < SS * 32; idx += 544) {
        float2 v = g_E2[idx];
        int s = idx >> 5, n1 = idx & 31;
        Er[s][n1] = v.x; Ei[s][n1] = v.y;
    }

    u64 aX[4][2];                 // [r][pair]
    u64 aY[2][2];                 // r=1 -> [0], r=3 -> [1]
#pragma unroll
    for (int r = 0; r < 4; r++) { aX[r][0] = aX[r][1] = 0ull; }
    aY[0][0] = aY[0][1] = aY[1][0] = aY[1][1] = 0ull;

    const float2* Tg = g_T + (size_t)bo * SS * MPAD;
    for (int c = 0; c < 2; c++) {
        __syncthreads();
        for (int idx = tid; idx < 32 * MPAD; idx += 544)
            ((float2*)Ts)[idx] = Tg[c * 32 * MPAD + idx];
        __syncthreads();

        for (int t = 0; t < 8; t++) {
#pragma unroll
            for (int r = 0; r < 4; r++) {
                int sl = 4 * t + r;
                int sgl = c * 32 + sl;
                float2 tv = Ts[sl][m];
                u64 txx = bc2(tv.x), ntyy = bc2(-tv.y);
                const float* er = &Er[sgl][ng * 4];
                const float* ei = &Ei[sgl][ng * 4];
#pragma unroll
                for (int p = 0; p < 2; p++) {
                    u64 ex = ld2(er + 2 * p), ey = ld2(ei + 2 * p);
                    // X += tx*ex - ty*ey
                    fm2(aX[r][p], txx, ex); fm2(aX[r][p], ntyy, ey);
                    if (r & 1) {
                        // Y += tx*ey + ty*ex
                        u64 tyy = bc2(tv.y);
                        fm2(aY[r >> 1][p], txx, ey); fm2(aY[r >> 1][p], tyy, ex);
                    }
                }
            }
        }
    }

    if (m < WOUT) {
        float* op = out + (size_t)bo * HH * WOUT;
        const float sc = 1.0f / (128.0f * 65.0f);
#pragma unroll
        for (int p = 0; p < 2; p++) {
            float2 a0  = up2(aX[0][p]);
            float2 a1x = up2(aX[1][p]);
            float2 a2  = up2(aX[2][p]);
            float2 a3x = up2(aX[3][p]);
            float2 a1y = up2(aY[0][p]);
            float2 a3y = up2(aY[1][p]);
            int n1 = ng * 4 + 2 * p;
            // lo element
            {
                float v0 = a0.x + a1x.x + a2.x + a3x.x;
                float v1 = a0.x - a1y.x - a2.x + a3y.x;
                float v2 = a0.x - a1x.x + a2.x - a3x.x;
                float v3 = a0.x + a1y.x - a2.x - a3y.x;
                op[(size_t)(n1      ) * WOUT + m] = v0 * sc;
                op[(size_t)(n1 + 32 ) * WOUT + m] = v1 * sc;
                op[(size_t)(n1 + 64 ) * WOUT + m] = v2 * sc;
                op[(size_t)(n1 + 96 ) * WOUT + m] = v3 * sc;
            }
            // hi element
            {
                int n1b = n1 + 1;
                float v0 = a0.y + a1x.y + a2.y + a3x.y;
                float v1 = a0.y - a1y.y - a2.y + a3y.y;
                float v2 = a0.y - a1x.y + a2.y - a3x.y;
                float v3 = a0.y + a1y.y - a2.y - a3y.y;
                op[(size_t)(n1b      ) * WOUT + m] = v0 * sc;
                op[(size_t)(n1b + 32 ) * WOUT + m] = v1 * sc;
                op[(size_t)(n1b + 64 ) * WOUT + m] = v2 * sc;
                op[(size_t)(n1b + 96 ) * WOUT + m] = v3 * sc;
            }
        }
    }
}

// ---------------- launch ----------------
extern "C" void kernel_launch(void* const* d_in, const int* in_sizes, int n_in,
                              void* d_out, int out_size) {
    (void)in_sizes; (void)n_in; (void)out_size;
    const float* x   = (const float*)d_in[0];
    const float* w1r = (const float*)d_in[1];
    const float* w1i = (const float*)d_in[2];
    const float* w2r = (const float*)d_in[3];
    const float* w2i = (const float*)d_in[4];
    float* out = (float*)d_out;

    k_fill<<<32, 256>>>();
    kW<<<SS * CI, 256>>>(w1r, w1i, w2r, w2i);        // 4096 blocks
    kA<<<(BB * CI * HH) / 32, 128>>>(x);            // 8192 blocks
    kB<<<BB * CI, 256>>>();                          // 2048 blocks
    kC<<<SS * M2, 128>>>();                          // 2048 blocks
    kD<<<SS * 64, 272>>>();                          // 4096 blocks
    kE<<<BB * CO, 544>>>(out);                       // 2048 blocks
}

// round 5
// speedup vs baseline: 1.0463x; 1.0463x over previous
#include <cuda_runtime.h>

// Problem constants
#define BB   32
#define CI   64
#define CO   64
#define HH   128
#define WW   128
#define M1   32
#define M2   32
#define SS   64      // retained kx rows: {0..31} U {96..127}
#define WOUT 65      // rfft width = W/2+1 = ifft length on last axis
#define MPAD 68      // m padded for tiling

typedef unsigned long long u64;
__device__ __forceinline__ u64 pk2(float lo, float hi){ u64 r; asm("mov.b64 %0,{%1,%2};" : "=l"(r) : "f"(lo), "f"(hi)); return r; }
__device__ __forceinline__ u64 bc2(float v){ return pk2(v, v); }
__device__ __forceinline__ void fm2(u64& d, u64 a, u64 b){ asm("fma.rn.f32x2 %0,%1,%2,%0;" : "+l"(d) : "l"(a), "l"(b)); }
__device__ __forceinline__ float2 up2(u64 v){ float2 r; asm("mov.b64 {%0,%1},%2;" : "=f"(r.x), "=f"(r.y) : "l"(v)); return r; }
__device__ __forceinline__ u64 ld2(const float* p){ return *(const u64*)p; }

// ---------------- scratch (device globals) ----------------
__device__ float2 g_Y[(size_t)BB * CI * HH * M2];    // stage A out: [bi][n][ky]
__device__ float2 g_X[(size_t)SS * M2 * BB * CI];    // stage B out: [mode][b*64+i]
__device__ float2 g_G[(size_t)SS * M2 * BB * CO];    // stage C out: [mode][b*64+o]
__device__ float2 g_T[(size_t)BB * CO * SS * MPAD];  // stage D out: [bo][s][m]
__device__ float2 g_W[(size_t)SS * M2 * CI * CO];    // transposed weights: [mode][i][o]

// twiddle tables
__device__ float2 g_FA[M2 * M2];     // [n1][ky]  e^{-2pi i ky n1/128}
__device__ float2 g_FB[SS * 32];     // [s][n1]   e^{-2pi i kx(s) n1/128}
__device__ float2 g_E2[SS * 32];     // [s][n1]   e^{+2pi i kx(s) n1/128}
__device__ float2 g_IKY[M2 * MPAD];  // [ky][m]   e^{+2pi i ky m/65}

// ---------------- twiddle fill ----------------
__global__ void k_fill() {
    int t  = blockIdx.x * blockDim.x + threadIdx.x;
    int NT = gridDim.x * blockDim.x;
    const double P2 = 6.283185307179586476925286766559;

    for (int idx = t; idx < M2 * M2; idx += NT) {
        int n1 = idx >> 5, ky = idx & 31;
        double a = -P2 * (double)((ky * n1) & 127) / 128.0;
        g_FA[idx] = make_float2((float)cos(a), (float)sin(a));
    }
    for (int idx = t; idx < SS * 32; idx += NT) {
        int s = idx >> 5, n1 = idx & 31;
        int kx = (s < 32) ? s : (s + 64);
        double a = -P2 * (double)((kx * n1) & 127) / 128.0;
        float c = (float)cos(a), sn = (float)sin(a);
        g_FB[idx] = make_float2(c, sn);
        g_E2[idx] = make_float2(c, -sn);
    }
    for (int idx = t; idx < M2 * MPAD; idx += NT) {
        int ky = idx / MPAD, m = idx % MPAD;
        double a = P2 * (double)((ky * m) % 65) / 65.0;
        g_IKY[idx] = make_float2((float)cos(a), (float)sin(a));
    }
}

// ---------------- kW: weight transpose -> g_W[mode][i][o] ----------------
__global__ __launch_bounds__(256) void kW(const float* __restrict__ w1r, const float* __restrict__ w1i,
                                          const float* __restrict__ w2r, const float* __restrict__ w2i) {
    __shared__ float2 tile[CO][33];
    int tid = threadIdx.x;
    int s = blockIdx.x >> 6, i = blockIdx.x & 63;
    const float* wr = (s < 32) ? w1r : w2r;
    const float* wi = (s < 32) ? w1i : w2i;
    int sm = s & 31;

    for (int idx = tid; idx < CO * M2; idx += 256) {
        int o = idx >> 5, ky = idx & 31;
        size_t g = ((size_t)(i * CO + o) * M1 + sm) * M2 + ky;
        tile[o][ky] = make_float2(wr[g], wi[g]);
    }
    __syncthreads();
    for (int idx = tid; idx < M2 * CO; idx += 256) {
        int ky = idx >> 6, o = idx & 63;
        g_W[((size_t)(s * 32 + ky) * CI + i) * CO + o] = tile[o][ky];
    }
}

// ---------------- Stage A: real DFT along W (128 -> 32), radix-4 + FFMA2 ----------------
// Block: 32 rows, 128 threads. ky = tid&31, rg = tid>>5; thread rows rg*8..rg*8+7 (4 pairs).
__global__ __launch_bounds__(128) void kA(const float* __restrict__ x) {
    __shared__ float ysr[4][32][34];   // [cls][n1][row], SoA real
    __shared__ float ysi[4][32][34];   // imag
    __shared__ float2 tws[32][32];     // [n1][ky]
    int tid = threadIdx.x;

    for (int idx = tid; idx < 1024; idx += 128)
        ((float2*)tws)[idx] = g_FA[idx];

    size_t rowBase = (size_t)blockIdx.x * 32;
#pragma unroll
    for (int it = 0; it < 8; it++) {
        int idx = tid + 128 * it;
        int row = idx >> 5, n1 = idx & 31;
        const float* xp = x + (rowBase + row) * WW;
        float x0 = xp[n1], x1 = xp[n1 + 32], x2 = xp[n1 + 64], x3 = xp[n1 + 96];
        float p = x0 + x2, q = x0 - x2, u = x1 + x3, v = x3 - x1;
        ysr[0][n1][row] = p + u; ysi[0][n1][row] = 0.f;
        ysr[2][n1][row] = p - u; ysi[2][n1][row] = 0.f;
        ysr[1][n1][row] = q;     ysi[1][n1][row] = v;
        ysr[3][n1][row] = q;     ysi[3][n1][row] = -v;
    }
    __syncthreads();

    int ky = tid & 31, rg = tid >> 5, cls = ky & 3;
    u64 aX[4], aY[4];
#pragma unroll
    for (int p = 0; p < 4; p++) { aX[p] = 0ull; aY[p] = 0ull; }

    for (int n1 = 0; n1 < 32; n1++) {
        float2 tw = tws[n1][ky];
        u64 txx = bc2(tw.x), tyy = bc2(tw.y), ntyy = bc2(-tw.y);
        const float* br = &ysr[cls][n1][rg * 8];
        const float* bi = &ysi[cls][n1][rg * 8];
#pragma unroll
        for (int p = 0; p < 4; p++) {
            u64 yr = ld2(br + 2 * p), yi = ld2(bi + 2 * p);
            fm2(aX[p], yr, txx); fm2(aX[p], yi, ntyy);
            fm2(aY[p], yr, tyy); fm2(aY[p], yi, txx);
        }
    }
#pragma unroll
    for (int p = 0; p < 4; p++) {
        float2 X = up2(aX[p]), Y = up2(aY[p]);
        size_t r0 = rowBase + rg * 8 + 2 * p;
        g_Y[r0 * M2 + ky]       = make_float2(X.x, Y.x);
        g_Y[(r0 + 1) * M2 + ky] = make_float2(X.y, Y.y);
    }
}

// ---------------- Stage B: complex DFT along H (128 -> 64), radix-4 + FFMA2 ----------------
// Block per bi, 256 threads. Warp sg: cls = sg&3, thalf = sg>>2.
// s = cls + 4*t, t = thalf*8 + {0..7} (4 adjacent t-pairs). tw SoA [n1][cls*16+t].
__global__ __launch_bounds__(256, 4) void kB() {
    __shared__ float2 ys[4][32][32];   // [cls][n1][ky] 32 KB
    __shared__ float twr[32][66];      // [n1][cls*16+t]
    __shared__ float twi[32][66];
    int tid = threadIdx.x;
    int bi  = blockIdx.x;
    const float2* Yg = g_Y + (size_t)bi * HH * M2;

    for (int idx = tid; idx < SS * 32; idx += 256) {
        int s = idx >> 5, n1 = idx & 31;
        float2 t = g_FB[idx];
        int col = (s & 3) * 16 + (s >> 2);
        twr[n1][col] = t.x; twi[n1][col] = t.y;
    }
#pragma unroll
    for (int it = 0; it < 4; it++) {
        int idx = tid + 256 * it;
        int n1 = idx >> 5, ky = idx & 31;
        float2 Y0 = Yg[n1 * 32 + ky];
        float2 Y1 = Yg[(n1 + 32) * 32 + ky];
        float2 Y2 = Yg[(n1 + 64) * 32 + ky];
        float2 Y3 = Yg[(n1 + 96) * 32 + ky];
        float2 a = make_float2(Y0.x + Y2.x, Y0.y + Y2.y);
        float2 b = make_float2(Y0.x - Y2.x, Y0.y - Y2.y);
        float2 c = make_float2(Y1.x + Y3.x, Y1.y + Y3.y);
        float2 d = make_float2(Y1.x - Y3.x, Y1.y - Y3.y);
        ys[0][n1][ky] = make_float2(a.x + c.x, a.y + c.y);
        ys[2][n1][ky] = make_float2(a.x - c.x, a.y - c.y);
        ys[1][n1][ky] = make_float2(b.x + d.y, b.y - d.x);
        ys[3][n1][ky] = make_float2(b.x - d.y, b.y + d.x);
    }
    __syncthreads();

    int ky = tid & 31, sg = tid >> 5;
    int cls = sg & 3, tbase = (sg >> 2) * 8;
    int col0 = cls * 16 + tbase;
    u64 aX[4], aY[4];
#pragma unroll
    for (int p = 0; p < 4; p++) { aX[p] = 0ull; aY[p] = 0ull; }

    for (int n1 = 0; n1 < 32; n1++) {
        float2 y = ys[cls][n1][ky];
        u64 yxx = bc2(y.x), yyy = bc2(y.y), nyy = bc2(-y.y);
        const float* tr = &twr[n1][col0];
        const float* ti = &twi[n1][col0];
#pragma unroll
        for (int p = 0; p < 4; p++) {
            u64 tx = ld2(tr + 2 * p), ty = ld2(ti + 2 * p);
            // X += yx*tx - yy*ty ; Y += yx*ty + yy*tx
            fm2(aX[p], yxx, tx); fm2(aX[p], nyy, ty);
            fm2(aY[p], yxx, ty); fm2(aY[p], yyy, tx);
        }
    }
#pragma unroll
    for (int p = 0; p < 4; p++) {
        float2 X = up2(aX[p]), Y = up2(aY[p]);
        int t0 = tbase + 2 * p;
        int s0 = cls + 4 * t0, s1 = s0 + 4;
        g_X[((size_t)(s0 * 32 + ky)) * (BB * CI) + bi] = make_float2(X.x, Y.x);
        g_X[((size_t)(s1 * 32 + ky)) * (BB * CI) + bi] = make_float2(X.y, Y.y);
    }
}

// ---------------- Stage C: per-mode channel mix G = X * conj(W), FFMA2 ----------------
// Block per mode, 128 threads: o = tid&31 (covers o, o+32), bg = tid>>5; b = bg*8..bg*8+7.
__global__ __launch_bounds__(128, 6) void kC() {
    __shared__ float Xr[32][34];    // [il][b] SoA
    __shared__ float Xi[32][34];
    __shared__ float2 Ws[32][CO];   // [il][o]
    int tid  = threadIdx.x;
    int mode = blockIdx.x;

    const float2* Xg = g_X + (size_t)mode * (BB * CI);
    const float2* Wg = g_W + (size_t)mode * (CI * CO);

    int o = tid & 31, bg = tid >> 5;
    u64 aX0[4], aY0[4], aX1[4], aY1[4];
#pragma unroll
    for (int p = 0; p < 4; p++) { aX0[p] = aY0[p] = aX1[p] = aY1[p] = 0ull; }

    for (int c = 0; c < 2; c++) {
        __syncthreads();
        for (int idx = tid; idx < BB * 32; idx += 128) {
            int b = idx >> 5, il = idx & 31;
            float2 v = Xg[b * CI + c * 32 + il];
            Xr[il][b] = v.x; Xi[il][b] = v.y;
        }
        for (int idx = tid; idx < 32 * CO; idx += 128)
            ((float2*)Ws)[idx] = Wg[c * 32 * CO + idx];
        __syncthreads();

        for (int il = 0; il < 32; il++) {
            float2 w0 = Ws[il][o];
            float2 w1 = Ws[il][o + 32];
            u64 w0rr = bc2(w0.x), w0ii = bc2(w0.y), nw0ii = bc2(-w0.y);
            u64 w1rr = bc2(w1.x), w1ii = bc2(w1.y), nw1ii = bc2(-w1.y);
            const float* xr = &Xr[il][bg * 8];
            const float* xi = &Xi[il][bg * 8];
#pragma unroll
            for (int p = 0; p < 4; p++) {
                u64 xr01 = ld2(xr + 2 * p), xi01 = ld2(xi + 2 * p);
                // X += xr*wr + xi*wi ; Y += xi*wr - xr*wi
                fm2(aX0[p], xr01, w0rr); fm2(aX0[p], xi01, w0ii);
                fm2(aY0[p], xi01, w0rr); fm2(aY0[p], xr01, nw0ii);
                fm2(aX1[p], xr01, w1rr); fm2(aX1[p], xi01, w1ii);
                fm2(aY1[p], xi01, w1rr); fm2(aY1[p], xr01, nw1ii);
            }
        }
    }
    float2* Gp = g_G + (size_t)mode * (BB * CO);
#pragma unroll
    for (int p = 0; p < 4; p++) {
        int b0 = bg * 8 + 2 * p;
        float2 X0 = up2(aX0[p]), Y0 = up2(aY0[p]);
        float2 X1 = up2(aX1[p]), Y1 = up2(aY1[p]);
        Gp[b0 * CO + o]            = make_float2(X0.x, Y0.x);
        Gp[(b0 + 1) * CO + o]      = make_float2(X0.y, Y0.y);
        Gp[b0 * CO + o + 32]       = make_float2(X1.x, Y1.x);
        Gp[(b0 + 1) * CO + o + 32] = make_float2(X1.y, Y1.y);
    }
}

// ---------------- Stage D: inverse length-65 DFT along ky (32 -> 68), FFMA2 ----------------
// Block per (s, 32-wide bo chunk). 272 threads: m = tid%68, bg = tid/68; bo_local = bg*8..+7.
__global__ __launch_bounds__(272, 4) void kD() {
    __shared__ float Gr[M2][34];      // [ky][bo_local] SoA
    __shared__ float Gi[M2][34];
    __shared__ float2 Ks[M2][MPAD];
    int tid = threadIdx.x;
    int s  = blockIdx.x >> 6;
    int cb = blockIdx.x & 63;
    int bo0 = cb * 32;

    for (int idx = tid; idx < M2 * 32; idx += 272) {
        int ky = idx >> 5, bol = idx & 31;
        float2 v = g_G[(size_t)(s * 32 + ky) * (BB * CO) + bo0 + bol];
        Gr[ky][bol] = v.x; Gi[ky][bol] = v.y;
    }
    for (int idx = tid; idx < M2 * MPAD; idx += 272)
        ((float2*)Ks)[idx] = g_IKY[idx];
    __syncthreads();

    int m = tid % MPAD, bg = tid / MPAD;
    u64 aX[4], aY[4];
#pragma unroll
    for (int p = 0; p < 4; p++) { aX[p] = 0ull; aY[p] = 0ull; }

    for (int ky = 0; ky < M2; ky++) {
        float2 e = Ks[ky][m];
        u64 exx = bc2(e.x), eyy = bc2(e.y), neyy = bc2(-e.y);
        const float* gr = &Gr[ky][bg * 8];
        const float* gi = &Gi[ky][bg * 8];
#pragma unroll
        for (int p = 0; p < 4; p++) {
            u64 gx = ld2(gr + 2 * p), gy = ld2(gi + 2 * p);
            // X += gx*ex - gy*ey ; Y += gx*ey + gy*ex
            fm2(aX[p], gx, exx); fm2(aX[p], gy, neyy);
            fm2(aY[p], gx, eyy); fm2(aY[p], gy, exx);
        }
    }
#pragma unroll
    for (int p = 0; p < 4; p++) {
        float2 X = up2(aX[p]), Y = up2(aY[p]);
        int b0 = bo0 + bg * 8 + 2 * p;
        g_T[((size_t)b0 * SS + s) * MPAD + m]       = make_float2(X.x, Y.x);
        g_T[((size_t)(b0 + 1) * SS + s) * MPAD + m] = make_float2(X.y, Y.y);
    }
}

// ---------------- Stage E: inverse DFT along kx, radix-4 grouped, FFMA2, real part ----------------
// 544 threads: m = tid%68, ng = tid/68; n1 = ng*4 + {0..3} (2 adjacent pairs).
// Classes r=0,2 need only Re accumulators.
__global__ __launch_bounds__(544, 2) void kE(float* __restrict__ out) {
    __shared__ float2 Ts[32][MPAD];   // 17.4 KB
    __shared__ float Er[SS][32];      // [s][n1] SoA
    __shared__ float Ei[SS][32];
    int tid = threadIdx.x;
    int bo  = blockIdx.x;
    int m = tid % MPAD, ng = tid / MPAD;

    for (int idx = tid; idx < SS * 32; idx += 544) {
        float2 v = g_E2[idx];
        int s = idx >> 5, n1 = idx & 31;
        Er[s][n1] = v.x; Ei[s][n1] = v.y;
    }

    u64 aX[4][2];                 // [r][pair]
    u64 aY[2][2];                 // r=1 -> [0], r=3 -> [1]
#pragma unroll
    for (int r = 0; r < 4; r++) { aX[r][0] = aX[r][1] = 0ull; }
    aY[0][0] = aY[0][1] = aY[1][0] = aY[1][1] = 0ull;

    const float2* Tg = g_T + (size_t)bo * SS * MPAD;
    for (int c = 0; c < 2; c++) {
        __syncthreads();
        for (int idx = tid; idx < 32 * MPAD; idx += 544)
            ((float2*)Ts)[idx] = Tg[c * 32 * MPAD + idx];
        __syncthreads();

        for (int t = 0; t < 8; t++) {
#pragma unroll
            for (int r = 0; r < 4; r++) {
                int sl = 4 * t + r;
                int sgl = c * 32 + sl;
                float2 tv = Ts[sl][m];
                u64 txx = bc2(tv.x), ntyy = bc2(-tv.y);
                const float* er = &Er[sgl][ng * 4];
                const float* ei = &Ei[sgl][ng * 4];
#pragma unroll
                for (int p = 0; p < 2; p++) {
                    u64 ex = ld2(er + 2 * p), ey = ld2(ei + 2 * p);
                    // X += tx*ex - ty*ey
                    fm2(aX[r][p], txx, ex); fm2(aX[r][p], ntyy, ey);
                    if (r & 1) {
                        // Y += tx*ey + ty*ex
                        u64 tyy = bc2(tv.y);
                        fm2(aY[r >> 1][p], txx, ey); fm2(aY[r >> 1][p], tyy, ex);
                    }
                }
            }
        }
    }

    if (m < WOUT) {
        float* op = out + (size_t)bo * HH * WOUT;
        const float sc = 1.0f / (128.0f * 65.0f);
#pragma unroll
        for (int p = 0; p < 2; p++) {
            float2 a0  = up2(aX[0][p]);
            float2 a1x = up2(aX[1][p]);
            float2 a2  = up2(aX[2][p]);
            float2 a3x = up2(aX[3][p]);
            float2 a1y = up2(aY[0][p]);
            float2 a3y = up2(aY[1][p]);
            int n1 = ng * 4 + 2 * p;
            // lo element
            {
                float v0 = a0.x + a1x.x + a2.x + a3x.x;
                float v1 = a0.x - a1y.x - a2.x + a3y.x;
                float v2 = a0.x - a1x.x + a2.x - a3x.x;
                float v3 = a0.x + a1y.x - a2.x - a3y.x;
                op[(size_t)(n1      ) * WOUT + m] = v0 * sc;
                op[(size_t)(n1 + 32 ) * WOUT + m] = v1 * sc;
                op[(size_t)(n1 + 64 ) * WOUT + m] = v2 * sc;
                op[(size_t)(n1 + 96 ) * WOUT + m] = v3 * sc;
            }
            // hi element
            {
                int n1b = n1 + 1;
                float v0 = a0.y + a1x.y + a2.y + a3x.y;
                float v1 = a0.y - a1y.y - a2.y + a3y.y;
                float v2 = a0.y - a1x.y + a2.y - a3x.y;
                float v3 = a0.y + a1y.y - a2.y - a3y.y;
                op[(size_t)(n1b      ) * WOUT + m] = v0 * sc;
                op[(size_t)(n1b + 32 ) * WOUT + m] = v1 * sc;
                op[(size_t)(n1b + 64 ) * WOUT + m] = v2 * sc;
                op[(size_t)(n1b + 96 ) * WOUT + m] = v3 * sc;
            }
        }
    }
}

// ---------------- launch ----------------
extern "C" void kernel_launch(void* const* d_in, const int* in_sizes, int n_in,
                              void* d_out, int out_size) {
    (void)in_sizes; (void)n_in; (void)out_size;
    const float* x   = (const float*)d_in[0];
    const float* w1r = (const float*)d_in[1];
    const float* w1i = (const float*)d_in[2];
    const float* w2r = (const float*)d_in[3];
    const float* w2i = (const float*)d_in[4];
    float* out = (float*)d_out;

    k_fill<<<32, 256>>>();
    kW<<<SS * CI, 256>>>(w1r, w1i, w2r, w2i);        // 4096 blocks
    kA<<<(BB * CI * HH) / 32, 128>>>(x);            // 8192 blocks
    kB<<<BB * CI, 256>>>();                          // 2048 blocks
    kC<<<SS * M2, 128>>>();                          // 2048 blocks
    kD<<<SS * 64, 272>>>();                          // 4096 blocks
    kE<<<BB * CO, 544>>>(out);                       // 2048 blocks
}

// round 7
// speedup vs baseline: 1.4586x; 1.3941x over previous
#include <cuda_runtime.h>

// Problem constants
#define BB   32
#define CI   64
#define CO   64
#define HH   128
#define WW   128
#define M1   32
#define M2   32
#define SS   64      // retained kx rows: {0..31} U {96..127}
#define WOUT 65      // rfft width = W/2+1 = ifft length on last axis
#define MPAD 68      // m padded for tiling

// ---------------- scratch (device globals) ----------------
__device__ float2 g_Y[(size_t)BB * CI * HH * M2];    // stage A out: [bi][n][ky]
__device__ float2 g_X[(size_t)SS * M2 * BB * CI];    // stage B out: [mode][b*64+i]
__device__ float2 g_G[(size_t)SS * M2 * BB * CO];    // stage C out: [mode][b*64+o]
__device__ float2 g_T[(size_t)BB * CO * SS * MPAD];  // stage D out: [bo][s][m]
__device__ float2 g_W[(size_t)SS * M2 * CI * CO];    // transposed weights: [mode][i][o]

// twiddle tables
__device__ float2 g_FA[M2 * M2];     // [n1][ky]  e^{-2pi i ky n1/128}
__device__ float2 g_FB[SS * 32];     // [s][n1]   e^{-2pi i kx(s) n1/128}
__device__ float2 g_E2[SS * 32];     // [s][n1]   e^{+2pi i kx(s) n1/128}
__device__ float2 g_IKY[M2 * MPAD];  // [ky][m]   e^{+2pi i ky m/65}

// ---------------- twiddle fill ----------------
__global__ void k_fill() {
    int t  = blockIdx.x * blockDim.x + threadIdx.x;
    int NT = gridDim.x * blockDim.x;
    const double P2 = 6.283185307179586476925286766559;

    for (int idx = t; idx < M2 * M2; idx += NT) {
        int n1 = idx >> 5, ky = idx & 31;
        double a = -P2 * (double)((ky * n1) & 127) / 128.0;
        g_FA[idx] = make_float2((float)cos(a), (float)sin(a));
    }
    for (int idx = t; idx < SS * 32; idx += NT) {
        int s = idx >> 5, n1 = idx & 31;
        int kx = (s < 32) ? s : (s + 64);
        double a = -P2 * (double)((kx * n1) & 127) / 128.0;
        float c = (float)cos(a), sn = (float)sin(a);
        g_FB[idx] = make_float2(c, sn);
        g_E2[idx] = make_float2(c, -sn);
    }
    for (int idx = t; idx < M2 * MPAD; idx += NT) {
        int ky = idx / MPAD, m = idx % MPAD;
        double a = P2 * (double)((ky * m) % 65) / 65.0;
        g_IKY[idx] = make_float2((float)cos(a), (float)sin(a));
    }
}

// ---------------- kW: weight transpose -> g_W[mode][i][o] ----------------
__global__ __launch_bounds__(256) void kW(const float* __restrict__ w1r, const float* __restrict__ w1i,
                                          const float* __restrict__ w2r, const float* __restrict__ w2i) {
    __shared__ float2 tile[CO][33];
    int tid = threadIdx.x;
    int s = blockIdx.x >> 6, i = blockIdx.x & 63;
    const float* wr = (s < 32) ? w1r : w2r;
    const float* wi = (s < 32) ? w1i : w2i;
    int sm = s & 31;

    for (int idx = tid; idx < CO * M2; idx += 256) {
        int o = idx >> 5, ky = idx & 31;
        size_t g = ((size_t)(i * CO + o) * M1 + sm) * M2 + ky;
        tile[o][ky] = make_float2(wr[g], wi[g]);
    }
    __syncthreads();
    for (int idx = tid; idx < M2 * CO; idx += 256) {
        int ky = idx >> 6, o = idx & 63;
        g_W[((size_t)(s * 32 + ky) * CI + i) * CO + o] = tile[o][ky];
    }
}

// ---------------- Stage A: real DFT along W (128 -> 32), radix-4 folded ----------------
__global__ __launch_bounds__(256, 5) void kA(const float* __restrict__ x) {
    __shared__ float2 ys[32][4][33];   // [row][class][n1]
    __shared__ float2 tws[32][32];     // [n1][ky]
    int tid = threadIdx.x;

    for (int idx = tid; idx < 32 * 32; idx += 256)
        ((float2*)tws)[idx] = g_FA[idx];

    size_t rowBase = (size_t)blockIdx.x * 32;
#pragma unroll
    for (int it = 0; it < 4; it++) {
        int idx = tid + 256 * it;
        int row = idx >> 5, n1 = idx & 31;
        const float* xp = x + (rowBase + row) * WW;
        float x0 = xp[n1], x1 = xp[n1 + 32], x2 = xp[n1 + 64], x3 = xp[n1 + 96];
        float p = x0 + x2, q = x0 - x2, u = x1 + x3, v = x3 - x1;
        ys[row][0][n1] = make_float2(p + u, 0.f);
        ys[row][2][n1] = make_float2(p - u, 0.f);
        ys[row][1][n1] = make_float2(q,  v);
        ys[row][3][n1] = make_float2(q, -v);
    }
    __syncthreads();

    int ky = tid & 31, rg = tid >> 5;
    int cls = ky & 3;                  // stage A: DFT along W, output freq = ky -> class = ky&3
    float2 acc[4];
#pragma unroll
    for (int j = 0; j < 4; j++) acc[j] = make_float2(0.f, 0.f);

    for (int n1 = 0; n1 < 32; n1++) {
        float2 tw = tws[n1][ky];
#pragma unroll
        for (int j = 0; j < 4; j++) {
            float2 y = ys[rg + 8 * j][cls][n1];
            acc[j].x = fmaf(y.x, tw.x, fmaf(-y.y, tw.y, acc[j].x));
            acc[j].y = fmaf(y.x, tw.y, fmaf( y.y, tw.x, acc[j].y));
        }
    }
#pragma unroll
    for (int j = 0; j < 4; j++)
        g_Y[(rowBase + rg + 8 * j) * M2 + ky] = acc[j];
}

// ---------------- Stage B: complex DFT along H (128 -> 64), radix-4, ky-pair blocked ----------------
// Block per (b,i). 128 threads: kh = tid&15 -> ky pair {2kh, 2kh+1}; sg = tid>>4 -> s = sg+8j.
// FIX vs round 5: class = s & 3 (= sg & 3, constant per thread), NOT ky & 3. The fold
// is along n (H), so the decimation class is the OUTPUT kx residue.
__global__ __launch_bounds__(128) void kB() {
    __shared__ float2 ys[4][32][32];   // [class][n1][ky] 32 KB
    __shared__ float2 tws[SS][32];     // [s][n1] 16 KB
    int tid = threadIdx.x;
    int bi  = blockIdx.x;
    const float2* Yg = g_Y + (size_t)bi * HH * M2;

    for (int idx = tid; idx < SS * 32; idx += 128)
        ((float2*)tws)[idx] = g_FB[idx];

#pragma unroll
    for (int it = 0; it < 8; it++) {
        int idx = tid + 128 * it;
        int n1 = idx >> 5, ky = idx & 31;
        float2 Y0 = Yg[n1 * 32 + ky];
        float2 Y1 = Yg[(n1 + 32) * 32 + ky];
        float2 Y2 = Yg[(n1 + 64) * 32 + ky];
        float2 Y3 = Yg[(n1 + 96) * 32 + ky];
        float2 a = make_float2(Y0.x + Y2.x, Y0.y + Y2.y);
        float2 b = make_float2(Y0.x - Y2.x, Y0.y - Y2.y);
        float2 c = make_float2(Y1.x + Y3.x, Y1.y + Y3.y);
        float2 d = make_float2(Y1.x - Y3.x, Y1.y - Y3.y);
        ys[0][n1][ky] = make_float2(a.x + c.x, a.y + c.y);
        ys[2][n1][ky] = make_float2(a.x - c.x, a.y - c.y);
        ys[1][n1][ky] = make_float2(b.x + d.y, b.y - d.x);
        ys[3][n1][ky] = make_float2(b.x - d.y, b.y + d.x);
    }
    __syncthreads();

    int kh = tid & 15, sg = tid >> 4;
    int ky0 = 2 * kh, ky1 = ky0 + 1;
    int cls = sg & 3;                  // s = sg + 8j -> s&3 = sg&3 for all j
    float2 a0[8], a1[8];
#pragma unroll
    for (int j = 0; j < 8; j++) { a0[j] = make_float2(0.f, 0.f); a1[j] = make_float2(0.f, 0.f); }

    for (int n1 = 0; n1 < 32; n1++) {
        float2 y0 = ys[cls][n1][ky0];
        float2 y1 = ys[cls][n1][ky1];
#pragma unroll
        for (int j = 0; j < 8; j++) {
            float2 tw = tws[sg + 8 * j][n1];
            a0[j].x = fmaf(y0.x, tw.x, fmaf(-y0.y, tw.y, a0[j].x));
            a0[j].y = fmaf(y0.x, tw.y, fmaf( y0.y, tw.x, a0[j].y));
            a1[j].x = fmaf(y1.x, tw.x, fmaf(-y1.y, tw.y, a1[j].x));
            a1[j].y = fmaf(y1.x, tw.y, fmaf( y1.y, tw.x, a1[j].y));
        }
    }
#pragma unroll
    for (int j = 0; j < 8; j++) {
        int s = sg + 8 * j;
        g_X[((size_t)(s * 32 + ky0)) * (BB * CI) + bi] = a0[j];
        g_X[((size_t)(s * 32 + ky1)) * (BB * CI) + bi] = a1[j];
    }
}

// ---------------- Stage C: per-mode channel mix G = X * conj(W) ----------------
__global__ __launch_bounds__(128, 7) void kC() {
    __shared__ float2 Xs[BB][32];   // [b][i_local] 8 KB
    __shared__ float2 Ws[32][CO];   // [i_local][o] 16 KB
    int tid  = threadIdx.x;
    int mode = blockIdx.x;

    const float2* Xg = g_X + (size_t)mode * (BB * CI);
    const float2* Wg = g_W + (size_t)mode * (CI * CO);

    int o = tid & 31, bg = tid >> 5;
    float2 acc[16];
#pragma unroll
    for (int k = 0; k < 16; k++) acc[k] = make_float2(0.f, 0.f);

    for (int c = 0; c < 2; c++) {
        __syncthreads();
        for (int idx = tid; idx < BB * 32; idx += 128) {
            int b = idx >> 5, il = idx & 31;
            Xs[b][il] = Xg[b * CI + c * 32 + il];
        }
        for (int idx = tid; idx < 32 * CO; idx += 128)
            ((float2*)Ws)[idx] = Wg[c * 32 * CO + idx];
        __syncthreads();

        for (int il = 0; il < 32; il++) {
            float2 w0 = Ws[il][o];
            float2 w1 = Ws[il][o + 32];
#pragma unroll
            for (int k = 0; k < 8; k++) {
                float2 xv = Xs[bg + 4 * k][il];
                acc[k].x      = fmaf(xv.x, w0.x, fmaf( xv.y, w0.y, acc[k].x));
                acc[k].y      = fmaf(xv.y, w0.x, fmaf(-xv.x, w0.y, acc[k].y));
                acc[k + 8].x  = fmaf(xv.x, w1.x, fmaf( xv.y, w1.y, acc[k + 8].x));
                acc[k + 8].y  = fmaf(xv.y, w1.x, fmaf(-xv.x, w1.y, acc[k + 8].y));
            }
        }
    }
    float2* Gp = g_G + (size_t)mode * (BB * CO);
#pragma unroll
    for (int k = 0; k < 8; k++) {
        int b = bg + 4 * k;
        Gp[b * CO + o]      = acc[k];
        Gp[b * CO + o + 32] = acc[k + 8];
    }
}

// ---------------- Stage D: inverse length-65 DFT along ky (32 -> 68), m-pair blocked ----------------
// Block per (s, 32-wide bo chunk). 272 threads: mh = tid%34 -> m pair {2mh,2mh+1}; bg = tid/34.
__global__ __launch_bounds__(272, 4) void kD() {
    __shared__ float2 Gs[M2][33];     // [ky][bo_local]
    __shared__ float2 Ks[M2][MPAD];   // [ky][m]
    int tid = threadIdx.x;
    int s  = blockIdx.x >> 6;
    int cb = blockIdx.x & 63;
    int bo0 = cb * 32;

    for (int idx = tid; idx < M2 * 32; idx += 272) {
        int ky = idx >> 5, bol = idx & 31;
        Gs[ky][bol] = g_G[(size_t)(s * 32 + ky) * (BB * CO) + bo0 + bol];
    }
    for (int idx = tid; idx < M2 * MPAD; idx += 272)
        ((float2*)Ks)[idx] = g_IKY[idx];
    __syncthreads();

    int mh = tid % 34, bg = tid / 34;   // bg 0..7
    int m0 = 2 * mh;
    float2 aA[4], aB[4];                // m0 / m0+1, 4 bo each
#pragma unroll
    for (int j = 0; j < 4; j++) { aA[j] = make_float2(0.f, 0.f); aB[j] = make_float2(0.f, 0.f); }

    for (int ky = 0; ky < M2; ky++) {
        float4 ee = *(const float4*)&Ks[ky][m0];   // (e0.x,e0.y,e1.x,e1.y)
#pragma unroll
        for (int j = 0; j < 4; j++) {
            float2 g = Gs[ky][bg + 8 * j];
            aA[j].x = fmaf(g.x, ee.x, fmaf(-g.y, ee.y, aA[j].x));
            aA[j].y = fmaf(g.x, ee.y, fmaf( g.y, ee.x, aA[j].y));
            aB[j].x = fmaf(g.x, ee.z, fmaf(-g.y, ee.w, aB[j].x));
            aB[j].y = fmaf(g.x, ee.w, fmaf( g.y, ee.z, aB[j].y));
        }
    }
#pragma unroll
    for (int j = 0; j < 4; j++) {
        int bo = bo0 + bg + 8 * j;
        *(float4*)&g_T[((size_t)bo * SS + s) * MPAD + m0] =
            make_float4(aA[j].x, aA[j].y, aB[j].x, aB[j].y);
    }
}

// ---------------- Stage E: inverse DFT along kx, radix-4 grouped, m-pair blocked, real part ----------------
// 272 threads: mh = tid%34 -> m pair {2mh,2mh+1}; ng = tid/34 -> n1 = ng+8jn.
// Class r = s&3 (s = c*32 + 4t + r, and 32 ≡ 0 mod 4 so r = s&3). Im accs only for r in {1,3}.
__global__ __launch_bounds__(272) void kE(float* __restrict__ out) {
    __shared__ float2 Ts[32][MPAD];   // 17.4 KB
    __shared__ float2 Es[SS][32];     // 16 KB
    int tid = threadIdx.x;
    int bo  = blockIdx.x;
    int mh = tid % 34, ng = tid / 34;
    int m0 = 2 * mh, m1 = m0 + 1;

    for (int idx = tid; idx < SS * 32; idx += 272)
        ((float2*)Es)[idx] = g_E2[idx];

    float2 aX[4][4];   // [r][jn], .x=m0 .y=m1 (real part)
    float2 aY[2][4];   // r=1 -> [0], r=3 -> [1] (imag part)
#pragma unroll
    for (int r = 0; r < 4; r++)
#pragma unroll
        for (int j = 0; j < 4; j++) aX[r][j] = make_float2(0.f, 0.f);
#pragma unroll
    for (int r = 0; r < 2; r++)
#pragma unroll
        for (int j = 0; j < 4; j++) aY[r][j] = make_float2(0.f, 0.f);

    const float2* Tg = g_T + (size_t)bo * SS * MPAD;
    for (int c = 0; c < 2; c++) {
        __syncthreads();
        for (int idx = tid; idx < 32 * MPAD; idx += 272)
            ((float2*)Ts)[idx] = Tg[c * 32 * MPAD + idx];
        __syncthreads();

        for (int t = 0; t < 8; t++) {
#pragma unroll
            for (int r = 0; r < 4; r++) {
                int sl = 4 * t + r;
                int sgl = c * 32 + sl;
                float4 tq = *(const float4*)&Ts[sl][m0];   // (T0.x,T0.y,T1.x,T1.y)
#pragma unroll
                for (int jn = 0; jn < 4; jn++) {
                    float2 e = Es[sgl][ng + 8 * jn];
                    aX[r][jn].x = fmaf(tq.x, e.x, fmaf(-tq.y, e.y, aX[r][jn].x));
                    aX[r][jn].y = fmaf(tq.z, e.x, fmaf(-tq.w, e.y, aX[r][jn].y));
                    if (r & 1) {
                        aY[r >> 1][jn].x = fmaf(tq.x, e.y, fmaf(tq.y, e.x, aY[r >> 1][jn].x));
                        aY[r >> 1][jn].y = fmaf(tq.z, e.y, fmaf(tq.w, e.x, aY[r >> 1][jn].y));
                    }
                }
            }
        }
    }

    float* op = out + (size_t)bo * HH * WOUT;
    const float sc = 1.0f / (128.0f * 65.0f);
#pragma unroll
    for (int jn = 0; jn < 4; jn++) {
        int n1 = ng + 8 * jn;
        float a0m0 = aX[0][jn].x, a1m0 = aX[1][jn].x, a2m0 = aX[2][jn].x, a3m0 = aX[3][jn].x;
        float b1m0 = aY[0][jn].x, b3m0 = aY[1][jn].x;
        float a0m1 = aX[0][jn].y, a1m1 = aX[1][jn].y, a2m1 = aX[2][jn].y, a3m1 = aX[3][jn].y;
        float b1m1 = aY[0][jn].y, b3m1 = aY[1][jn].y;
        if (m0 < WOUT) {
            op[(size_t)(n1      ) * WOUT + m0] = (a0m0 + a1m0 + a2m0 + a3m0) * sc;
            op[(size_t)(n1 + 32 ) * WOUT + m0] = (a0m0 - b1m0 - a2m0 + b3m0) * sc;
            op[(size_t)(n1 + 64 ) * WOUT + m0] = (a0m0 - a1m0 + a2m0 - a3m0) * sc;
            op[(size_t)(n1 + 96 ) * WOUT + m0] = (a0m0 + b1m0 - a2m0 - b3m0) * sc;
        }
        if (m1 < WOUT) {
            op[(size_t)(n1      ) * WOUT + m1] = (a0m1 + a1m1 + a2m1 + a3m1) * sc;
            op[(size_t)(n1 + 32 ) * WOUT + m1] = (a0m1 - b1m1 - a2m1 + b3m1) * sc;
            op[(size_t)(n1 + 64 ) * WOUT + m1] = (a0m1 - a1m1 + a2m1 - a3m1) * sc;
            op[(size_t)(n1 + 96 ) * WOUT + m1] = (a0m1 + b1m1 - a2m1 - b3m1) * sc;
        }
    }
}

// ---------------- launch ----------------
extern "C" void kernel_launch(void* const* d_in, const int* in_sizes, int n_in,
                              void* d_out, int out_size) {
    (void)in_sizes; (void)n_in; (void)out_size;
    const float* x   = (const float*)d_in[0];
    const float* w1r = (const float*)d_in[1];
    const float* w1i = (const float*)d_in[2];
    const float* w2r = (const float*)d_in[3];
    const float* w2i = (const float*)d_in[4];
    float* out = (float*)d_out;

    k_fill<<<32, 256>>>();
    kW<<<SS * CI, 256>>>(w1r, w1i, w2r, w2i);        // 4096 blocks
    kA<<<(BB * CI * HH) / 32, 256>>>(x);            // 8192 blocks
    kB<<<BB * CI, 128>>>();                          // 2048 blocks
    kC<<<SS * M2, 128>>>();                          // 2048 blocks
    kD<<<SS * 64, 272>>>();                          // 4096 blocks
    kE<<<BB * CO, 272>>>(out);                       // 2048 blocks
}

// round 10
// speedup vs baseline: 1.4675x; 1.0061x over previous
#include <cuda_runtime.h>

// Problem constants
#define BB   32
#define CI   64
#define CO   64
#define HH   128
#define WW   128
#define M1   32
#define M2   32
#define SS   64      // retained kx rows: {0..31} U {96..127}
#define WOUT 65      // rfft width = W/2+1 = ifft length on last axis
#define MPAD 68      // m padded for tiling

// ---------------- scratch (device globals) ----------------
__device__ float2 g_Y[(size_t)BB * CI * HH * M2];    // stage A out: [bi][n][ky]
__device__ float2 g_X[(size_t)SS * M2 * BB * CI];    // stage B out: [mode][b*64+i]
__device__ float2 g_G[(size_t)SS * M2 * BB * CO];    // stage C out: [mode][b*64+o]
__device__ float2 g_T[(size_t)BB * CO * SS * MPAD];  // stage D out: [bo][s][m]
__device__ float2 g_W[(size_t)SS * M2 * CI * CO];    // transposed weights: [mode][i][o]

// twiddle tables
__device__ float2 g_FA[M2 * M2];     // [n1][ky]  e^{-2pi i ky n1/128}
__device__ float2 g_FB[SS * 32];     // [s][n1]   e^{-2pi i kx(s) n1/128}
__device__ float2 g_E2[SS * 32];     // [s][n1]   e^{+2pi i kx(s) n1/128}
__device__ float2 g_IKY[M2 * MPAD];  // [ky][m]   e^{+2pi i ky m/65}

// ---------------- twiddle fill ----------------
__global__ void k_fill() {
    int t  = blockIdx.x * blockDim.x + threadIdx.x;
    int NT = gridDim.x * blockDim.x;
    const double P2 = 6.283185307179586476925286766559;

    for (int idx = t; idx < M2 * M2; idx += NT) {
        int n1 = idx >> 5, ky = idx & 31;
        double a = -P2 * (double)((ky * n1) & 127) / 128.0;
        g_FA[idx] = make_float2((float)cos(a), (float)sin(a));
    }
    for (int idx = t; idx < SS * 32; idx += NT) {
        int s = idx >> 5, n1 = idx & 31;
        int kx = (s < 32) ? s : (s + 64);
        double a = -P2 * (double)((kx * n1) & 127) / 128.0;
        float c = (float)cos(a), sn = (float)sin(a);
        g_FB[idx] = make_float2(c, sn);
        g_E2[idx] = make_float2(c, -sn);
    }
    for (int idx = t; idx < M2 * MPAD; idx += NT) {
        int ky = idx / MPAD, m = idx % MPAD;
        double a = P2 * (double)((ky * m) % 65) / 65.0;
        g_IKY[idx] = make_float2((float)cos(a), (float)sin(a));
    }
}

// ---------------- kW: weight transpose -> g_W[mode][i][o] ----------------
__global__ __launch_bounds__(256) void kW(const float* __restrict__ w1r, const float* __restrict__ w1i,
                                          const float* __restrict__ w2r, const float* __restrict__ w2i) {
    __shared__ float2 tile[CO][33];
    int tid = threadIdx.x;
    int s = blockIdx.x >> 6, i = blockIdx.x & 63;
    const float* wr = (s < 32) ? w1r : w2r;
    const float* wi = (s < 32) ? w1i : w2i;
    int sm = s & 31;

    for (int idx = tid; idx < CO * M2; idx += 256) {
        int o = idx >> 5, ky = idx & 31;
        size_t g = ((size_t)(i * CO + o) * M1 + sm) * M2 + ky;
        tile[o][ky] = make_float2(wr[g], wi[g]);
    }
    __syncthreads();
    for (int idx = tid; idx < M2 * CO; idx += 256) {
        int ky = idx >> 6, o = idx & 63;
        g_W[((size_t)(s * 32 + ky) * CI + i) * CO + o] = tile[o][ky];
    }
}

// ---------------- Stage A: real DFT along W (128 -> 32), radix-4, row-contiguous tiles ----------------
// Block: 32 rows, 256 threads: ky = tid&31, rg = tid>>5 -> rows rg*4..rg*4+3 (2 LDS.128/n1).
// ys layout [cls][n1*34+row]; +2 float2 cls pad shifts each cls to a distinct bank quad.
#define KA_CSTRIDE (32 * 34 + 2)
__global__ __launch_bounds__(256, 5) void kA(const float* __restrict__ x) {
    __shared__ __align__(16) float2 ys[4][KA_CSTRIDE];   // ~34.9 KB
    __shared__ float2 tws[32][32];                       // [n1][ky] 8 KB
    int tid = threadIdx.x;

    for (int idx = tid; idx < 32 * 32; idx += 256)
        ((float2*)tws)[idx] = g_FA[idx];

    size_t rowBase = (size_t)blockIdx.x * 32;
#pragma unroll
    for (int it = 0; it < 4; it++) {
        int idx = tid + 256 * it;
        int row = idx >> 5, n1 = idx & 31;
        const float* xp = x + (rowBase + row) * WW;
        float x0 = xp[n1], x1 = xp[n1 + 32], x2 = xp[n1 + 64], x3 = xp[n1 + 96];
        float p = x0 + x2, q = x0 - x2, u = x1 + x3, v = x3 - x1;
        int base = n1 * 34 + row;
        ys[0][base] = make_float2(p + u, 0.f);
        ys[2][base] = make_float2(p - u, 0.f);
        ys[1][base] = make_float2(q,  v);
        ys[3][base] = make_float2(q, -v);
    }
    __syncthreads();

    int ky = tid & 31, rg = tid >> 5;
    int cls = ky & 3;                  // DFT along W, output freq = ky -> class = ky&3
    float2 acc[4];
#pragma unroll
    for (int j = 0; j < 4; j++) acc[j] = make_float2(0.f, 0.f);

    for (int n1 = 0; n1 < 32; n1++) {
        float2 tw = tws[n1][ky];
        const float4* yp = (const float4*)&ys[cls][n1 * 34 + rg * 4];
        float4 yA = yp[0], yB = yp[1];  // rows rg*4+0,1 and rg*4+2,3 (complex pairs)
        acc[0].x = fmaf(yA.x, tw.x, fmaf(-yA.y, tw.y, acc[0].x));
        acc[0].y = fmaf(yA.x, tw.y, fmaf( yA.y, tw.x, acc[0].y));
        acc[1].x = fmaf(yA.z, tw.x, fmaf(-yA.w, tw.y, acc[1].x));
        acc[1].y = fmaf(yA.z, tw.y, fmaf( yA.w, tw.x, acc[1].y));
        acc[2].x = fmaf(yB.x, tw.x, fmaf(-yB.y, tw.y, acc[2].x));
        acc[2].y = fmaf(yB.x, tw.y, fmaf( yB.y, tw.x, acc[2].y));
        acc[3].x = fmaf(yB.z, tw.x, fmaf(-yB.w, tw.y, acc[3].x));
        acc[3].y = fmaf(yB.z, tw.y, fmaf( yB.w, tw.x, acc[3].y));
    }
#pragma unroll
    for (int j = 0; j < 4; j++)
        g_Y[(rowBase + rg * 4 + j) * M2 + ky] = acc[j];
}

// ---------------- Stage B: complex DFT along H (128 -> 64), radix-4, ky-pair via LDS.128 ----------------
// Block per (b,i), 256 threads: kh = tid&15 -> ky pair {2kh,2kh+1}; sg = tid>>4 -> s = sg+16j (j<4).
// Class = s&3 = sg&3 (constant). y-pair = one LDS.128; tws padded [64][33] for bank spread.
__global__ __launch_bounds__(256) void kB() {
    __shared__ __align__(16) float2 ys[4][32][32];   // [cls][n1][ky] 32 KB, ky contiguous
    __shared__ float2 tws[SS][33];                   // [s][n1] ~16.9 KB
    int tid = threadIdx.x;
    int bi  = blockIdx.x;
    const float2* Yg = g_Y + (size_t)bi * HH * M2;

    for (int idx = tid; idx < SS * 32; idx += 256) {
        int s = idx >> 5, n1 = idx & 31;
        tws[s][n1] = g_FB[idx];
    }

#pragma unroll
    for (int it = 0; it < 4; it++) {
        int idx = tid + 256 * it;
        int n1 = idx >> 5, ky = idx & 31;
        float2 Y0 = Yg[n1 * 32 + ky];
        float2 Y1 = Yg[(n1 + 32) * 32 + ky];
        float2 Y2 = Yg[(n1 + 64) * 32 + ky];
        float2 Y3 = Yg[(n1 + 96) * 32 + ky];
        float2 a = make_float2(Y0.x + Y2.x, Y0.y + Y2.y);
        float2 b = make_float2(Y0.x - Y2.x, Y0.y - Y2.y);
        float2 c = make_float2(Y1.x + Y3.x, Y1.y + Y3.y);
        float2 d = make_float2(Y1.x - Y3.x, Y1.y - Y3.y);
        ys[0][n1][ky] = make_float2(a.x + c.x, a.y + c.y);
        ys[2][n1][ky] = make_float2(a.x - c.x, a.y - c.y);
        ys[1][n1][ky] = make_float2(b.x + d.y, b.y - d.x);
        ys[3][n1][ky] = make_float2(b.x - d.y, b.y + d.x);
    }
    __syncthreads();

    int kh = tid & 15, sg = tid >> 4;
    int ky0 = 2 * kh, ky1 = ky0 + 1;
    int cls = sg & 3;                  // s = sg + 16j -> s&3 = sg&3
    float2 a0[4], a1[4];
#pragma unroll
    for (int j = 0; j < 4; j++) { a0[j] = make_float2(0.f, 0.f); a1[j] = make_float2(0.f, 0.f); }

    for (int n1 = 0; n1 < 32; n1++) {
        float4 yq = *(const float4*)&ys[cls][n1][ky0];   // y(ky0)=(x,y), y(ky1)=(z,w)
#pragma unroll
        for (int j = 0; j < 4; j++) {
            float2 tw = tws[sg + 16 * j][n1];
            a0[j].x = fmaf(yq.x, tw.x, fmaf(-yq.y, tw.y, a0[j].x));
            a0[j].y = fmaf(yq.x, tw.y, fmaf( yq.y, tw.x, a0[j].y));
            a1[j].x = fmaf(yq.z, tw.x, fmaf(-yq.w, tw.y, a1[j].x));
            a1[j].y = fmaf(yq.z, tw.y, fmaf( yq.w, tw.x, a1[j].y));
        }
    }
#pragma unroll
    for (int j = 0; j < 4; j++) {
        int s = sg + 16 * j;
        g_X[((size_t)(s * 32 + ky0)) * (BB * CI) + bi] = a0[j];
        g_X[((size_t)(s * 32 + ky1)) * (BB * CI) + bi] = a1[j];
    }
}

// ---------------- Stage C: per-mode channel mix G = X * conj(W) ----------------
__global__ __launch_bounds__(128, 7) void kC() {
    __shared__ float2 Xs[BB][32];   // [b][i_local] 8 KB
    __shared__ float2 Ws[32][CO];   // [i_local][o] 16 KB
    int tid  = threadIdx.x;
    int mode = blockIdx.x;

    const float2* Xg = g_X + (size_t)mode * (BB * CI);
    const float2* Wg = g_W + (size_t)mode * (CI * CO);

    int o = tid & 31, bg = tid >> 5;
    float2 acc[16];
#pragma unroll
    for (int k = 0; k < 16; k++) acc[k] = make_float2(0.f, 0.f);

    for (int c = 0; c < 2; c++) {
        __syncthreads();
        for (int idx = tid; idx < BB * 32; idx += 128) {
            int b = idx >> 5, il = idx & 31;
            Xs[b][il] = Xg[b * CI + c * 32 + il];
        }
        for (int idx = tid; idx < 32 * CO; idx += 128)
            ((float2*)Ws)[idx] = Wg[c * 32 * CO + idx];
        __syncthreads();

        for (int il = 0; il < 32; il++) {
            float2 w0 = Ws[il][o];
            float2 w1 = Ws[il][o + 32];
#pragma unroll
            for (int k = 0; k < 8; k++) {
                float2 xv = Xs[bg + 4 * k][il];
                acc[k].x      = fmaf(xv.x, w0.x, fmaf( xv.y, w0.y, acc[k].x));
                acc[k].y      = fmaf(xv.y, w0.x, fmaf(-xv.x, w0.y, acc[k].y));
                acc[k + 8].x  = fmaf(xv.x, w1.x, fmaf( xv.y, w1.y, acc[k + 8].x));
                acc[k + 8].y  = fmaf(xv.y, w1.x, fmaf(-xv.x, w1.y, acc[k + 8].y));
            }
        }
    }
    float2* Gp = g_G + (size_t)mode * (BB * CO);
#pragma unroll
    for (int k = 0; k < 8; k++) {
        int b = bg + 4 * k;
        Gp[b * CO + o]      = acc[k];
        Gp[b * CO + o + 32] = acc[k + 8];
    }
}

// ---------------- Stage D: inverse length-65 DFT along ky (32 -> 68), m-pair blocked ----------------
__global__ __launch_bounds__(272, 4) void kD() {
    __shared__ float2 Gs[M2][33];     // [ky][bo_local]
    __shared__ __align__(16) float2 Ks[M2][MPAD];   // [ky][m]
    int tid = threadIdx.x;
    int s  = blockIdx.x >> 6;
    int cb = blockIdx.x & 63;
    int bo0 = cb * 32;

    for (int idx = tid; idx < M2 * 32; idx += 272) {
        int ky = idx >> 5, bol = idx & 31;
        Gs[ky][bol] = g_G[(size_t)(s * 32 + ky) * (BB * CO) + bo0 + bol];
    }
    for (int idx = tid; idx < M2 * MPAD; idx += 272)
        ((float2*)Ks)[idx] = g_IKY[idx];
    __syncthreads();

    int mh = tid % 34, bg = tid / 34;   // bg 0..7
    int m0 = 2 * mh;
    float2 aA[4], aB[4];                // m0 / m0+1, 4 bo each
#pragma unroll
    for (int j = 0; j < 4; j++) { aA[j] = make_float2(0.f, 0.f); aB[j] = make_float2(0.f, 0.f); }

    for (int ky = 0; ky < M2; ky++) {
        float4 ee = *(const float4*)&Ks[ky][m0];   // (e0.x,e0.y,e1.x,e1.y)
#pragma unroll
        for (int j = 0; j < 4; j++) {
            float2 g = Gs[ky][bg + 8 * j];
            aA[j].x = fmaf(g.x, ee.x, fmaf(-g.y, ee.y, aA[j].x));
            aA[j].y = fmaf(g.x, ee.y, fmaf( g.y, ee.x, aA[j].y));
            aB[j].x = fmaf(g.x, ee.z, fmaf(-g.y, ee.w, aB[j].x));
            aB[j].y = fmaf(g.x, ee.w, fmaf( g.y, ee.z, aB[j].y));
        }
    }
#pragma unroll
    for (int j = 0; j < 4; j++) {
        int bo = bo0 + bg + 8 * j;
        *(float4*)&g_T[((size_t)bo * SS + s) * MPAD + m0] =
            make_float4(aA[j].x, aA[j].y, aB[j].x, aB[j].y);
    }
}

// ---------------- Stage E: inverse DFT along kx, radix-4 grouped, m-pair blocked, real part ----------------
__global__ __launch_bounds__(272) void kE(float* __restrict__ out) {
    __shared__ __align__(16) float2 Ts[32][MPAD];   // 17.4 KB
    __shared__ float2 Es[SS][32];     // 16 KB
    int tid = threadIdx.x;
    int bo  = blockIdx.x;
    int mh = tid % 34, ng = tid / 34;
    int m0 = 2 * mh, m1 = m0 + 1;

    for (int idx = tid; idx < SS * 32; idx += 272)
        ((float2*)Es)[idx] = g_E2[idx];

    float2 aX[4][4];   // [r][jn], .x=m0 .y=m1 (real part)
    float2 aY[2][4];   // r=1 -> [0], r=3 -> [1] (imag part)
#pragma unroll
    for (int r = 0; r < 4; r++)
#pragma unroll
        for (int j = 0; j < 4; j++) aX[r][j] = make_float2(0.f, 0.f);
#pragma unroll
    for (int r = 0; r < 2; r++)
#pragma unroll
        for (int j = 0; j < 4; j++) aY[r][j] = make_float2(0.f, 0.f);

    const float2* Tg = g_T + (size_t)bo * SS * MPAD;
    for (int c = 0; c < 2; c++) {
        __syncthreads();
        for (int idx = tid; idx < 32 * MPAD; idx += 272)
            ((float2*)Ts)[idx] = Tg[c * 32 * MPAD + idx];
        __syncthreads();

        for (int t = 0; t < 8; t++) {
#pragma unroll
            for (int r = 0; r < 4; r++) {
                int sl = 4 * t + r;
                int sgl = c * 32 + sl;
                float4 tq = *(const float4*)&Ts[sl][m0];   // (T0.x,T0.y,T1.x,T1.y)
#pragma unroll
                for (int jn = 0; jn < 4; jn++) {
                    float2 e = Es[sgl][ng + 8 * jn];
                    aX[r][jn].x = fmaf(tq.x, e.x, fmaf(-tq.y, e.y, aX[r][jn].x));
                    aX[r][jn].y = fmaf(tq.z, e.x, fmaf(-tq.w, e.y, aX[r][jn].y));
                    if (r & 1) {
                        aY[r >> 1][jn].x = fmaf(tq.x, e.y, fmaf(tq.y, e.x, aY[r >> 1][jn].x));
                        aY[r >> 1][jn].y = fmaf(tq.z, e.y, fmaf(tq.w, e.x, aY[r >> 1][jn].y));
                    }
                }
            }
        }
    }

    float* op = out + (size_t)bo * HH * WOUT;
    const float sc = 1.0f / (128.0f * 65.0f);
#pragma unroll
    for (int jn = 0; jn < 4; jn++) {
        int n1 = ng + 8 * jn;
        float a0m0 = aX[0][jn].x, a1m0 = aX[1][jn].x, a2m0 = aX[2][jn].x, a3m0 = aX[3][jn].x;
        float b1m0 = aY[0][jn].x, b3m0 = aY[1][jn].x;
        float a0m1 = aX[0][jn].y, a1m1 = aX[1][jn].y, a2m1 = aX[2][jn].y, a3m1 = aX[3][jn].y;
        float b1m1 = aY[0][jn].y, b3m1 = aY[1][jn].y;
        if (m0 < WOUT) {
            op[(size_t)(n1      ) * WOUT + m0] = (a0m0 + a1m0 + a2m0 + a3m0) * sc;
            op[(size_t)(n1 + 32 ) * WOUT + m0] = (a0m0 - b1m0 - a2m0 + b3m0) * sc;
            op[(size_t)(n1 + 64 ) * WOUT + m0] = (a0m0 - a1m0 + a2m0 - a3m0) * sc;
            op[(size_t)(n1 + 96 ) * WOUT + m0] = (a0m0 + b1m0 - a2m0 - b3m0) * sc;
        }
        if (m1 < WOUT) {
            op[(size_t)(n1      ) * WOUT + m1] = (a0m1 + a1m1 + a2m1 + a3m1) * sc;
            op[(size_t)(n1 + 32 ) * WOUT + m1] = (a0m1 - b1m1 - a2m1 + b3m1) * sc;
            op[(size_t)(n1 + 64 ) * WOUT + m1] = (a0m1 - a1m1 + a2m1 - a3m1) * sc;
            op[(size_t)(n1 + 96 ) * WOUT + m1] = (a0m1 + b1m1 - a2m1 - b3m1) * sc;
        }
    }
}

// ---------------- launch ----------------
extern "C" void kernel_launch(void* const* d_in, const int* in_sizes, int n_in,
                              void* d_out, int out_size) {
    (void)in_sizes; (void)n_in; (void)out_size;
    const float* x   = (const float*)d_in[0];
    const float* w1r = (const float*)d_in[1];
    const float* w1i = (const float*)d_in[2];
    const float* w2r = (const float*)d_in[3];
    const float* w2i = (const float*)d_in[4];
    float* out = (float*)d_out;

    k_fill<<<32, 256>>>();
    kW<<<SS * CI, 256>>>(w1r, w1i, w2r, w2i);        // 4096 blocks
    kA<<<(BB * CI * HH) / 32, 256>>>(x);            // 8192 blocks
    kB<<<BB * CI, 256>>>();                          // 2048 blocks
    kC<<<SS * M2, 128>>>();                          // 2048 blocks
    kD<<<SS * 64, 272>>>();                          // 4096 blocks
    kE<<<BB * CO, 272>>>(out);                       // 2048 blocks
}

// round 11
// speedup vs baseline: 1.5533x; 1.0584x over previous
#include <cuda_runtime.h>

// Problem constants
#define BB   32
#define CI   64
#define CO   64
#define HH   128
#define WW   128
#define M1   32
#define M2   32
#define SS   64      // retained kx rows: {0..31} U {96..127}
#define WOUT 65      // rfft width = W/2+1 = ifft length on last axis
#define MPAD 68      // m padded for tiling

// ---------------- scratch (device globals) ----------------
__device__ float2 g_Y[(size_t)BB * CI * HH * M2];    // stage A out: [bi][n][ky]
__device__ float2 g_X[(size_t)SS * M2 * BB * CI];    // stage B out: [mode][b*64+i]
__device__ float2 g_G[(size_t)SS * M2 * BB * CO];    // stage C out: [mode][b*64+o]
__device__ float2 g_T[(size_t)BB * CO * SS * MPAD];  // stage D out: [bo][s][m]
__device__ float2 g_W[(size_t)SS * M2 * CI * CO];    // transposed weights: [mode][i][o]

// twiddle tables
__device__ float2 g_FA[M2 * M2];     // [n1][ky]  e^{-2pi i ky n1/128}
__device__ float2 g_FB[SS * 32];     // [s][n1]   e^{-2pi i kx(s) n1/128}
__device__ float2 g_E2[SS * 32];     // [s][n1]   e^{+2pi i kx(s) n1/128}
__device__ float2 g_IKY[M2 * MPAD];  // [ky][m]   e^{+2pi i ky m/65}

// ---------------- twiddle fill ----------------
__global__ void k_fill() {
    int t  = blockIdx.x * blockDim.x + threadIdx.x;
    int NT = gridDim.x * blockDim.x;
    const double P2 = 6.283185307179586476925286766559;

    for (int idx = t; idx < M2 * M2; idx += NT) {
        int n1 = idx >> 5, ky = idx & 31;
        double a = -P2 * (double)((ky * n1) & 127) / 128.0;
        g_FA[idx] = make_float2((float)cos(a), (float)sin(a));
    }
    for (int idx = t; idx < SS * 32; idx += NT) {
        int s = idx >> 5, n1 = idx & 31;
        int kx = (s < 32) ? s : (s + 64);
        double a = -P2 * (double)((kx * n1) & 127) / 128.0;
        float c = (float)cos(a), sn = (float)sin(a);
        g_FB[idx] = make_float2(c, sn);
        g_E2[idx] = make_float2(c, -sn);
    }
    for (int idx = t; idx < M2 * MPAD; idx += NT) {
        int ky = idx / MPAD, m = idx % MPAD;
        double a = P2 * (double)((ky * m) % 65) / 65.0;
        g_IKY[idx] = make_float2((float)cos(a), (float)sin(a));
    }
}

// ---------------- kW: weight transpose -> g_W[mode][i][o] ----------------
__global__ __launch_bounds__(256) void kW(const float* __restrict__ w1r, const float* __restrict__ w1i,
                                          const float* __restrict__ w2r, const float* __restrict__ w2i) {
    __shared__ float2 tile[CO][33];
    int tid = threadIdx.x;
    int s = blockIdx.x >> 6, i = blockIdx.x & 63;
    const float* wr = (s < 32) ? w1r : w2r;
    const float* wi = (s < 32) ? w1i : w2i;
    int sm = s & 31;

    for (int idx = tid; idx < CO * M2; idx += 256) {
        int o = idx >> 5, ky = idx & 31;
        size_t g = ((size_t)(i * CO + o) * M1 + sm) * M2 + ky;
        tile[o][ky] = make_float2(wr[g], wi[g]);
    }
    __syncthreads();
    for (int idx = tid; idx < M2 * CO; idx += 256) {
        int ky = idx >> 6, o = idx & 63;
        g_W[((size_t)(s * 32 + ky) * CI + i) * CO + o] = tile[o][ky];
    }
}

// ---------------- Stage A: real DFT along W (128 -> 32), radix-4, row-contiguous tiles ----------------
#define KA_CSTRIDE (32 * 34 + 2)
__global__ __launch_bounds__(256, 5) void kA(const float* __restrict__ x) {
    __shared__ __align__(16) float2 ys[4][KA_CSTRIDE];   // ~34.9 KB
    __shared__ float2 tws[32][32];                       // [n1][ky] 8 KB
    int tid = threadIdx.x;

    for (int idx = tid; idx < 32 * 32; idx += 256)
        ((float2*)tws)[idx] = g_FA[idx];

    size_t rowBase = (size_t)blockIdx.x * 32;
#pragma unroll
    for (int it = 0; it < 4; it++) {
        int idx = tid + 256 * it;
        int row = idx >> 5, n1 = idx & 31;
        const float* xp = x + (rowBase + row) * WW;
        float x0 = xp[n1], x1 = xp[n1 + 32], x2 = xp[n1 + 64], x3 = xp[n1 + 96];
        float p = x0 + x2, q = x0 - x2, u = x1 + x3, v = x3 - x1;
        int base = n1 * 34 + row;
        ys[0][base] = make_float2(p + u, 0.f);
        ys[2][base] = make_float2(p - u, 0.f);
        ys[1][base] = make_float2(q,  v);
        ys[3][base] = make_float2(q, -v);
    }
    __syncthreads();

    int ky = tid & 31, rg = tid >> 5;
    int cls = ky & 3;
    float2 acc[4];
#pragma unroll
    for (int j = 0; j < 4; j++) acc[j] = make_float2(0.f, 0.f);

    for (int n1 = 0; n1 < 32; n1++) {
        float2 tw = tws[n1][ky];
        const float4* yp = (const float4*)&ys[cls][n1 * 34 + rg * 4];
        float4 yA = yp[0], yB = yp[1];
        acc[0].x = fmaf(yA.x, tw.x, fmaf(-yA.y, tw.y, acc[0].x));
        acc[0].y = fmaf(yA.x, tw.y, fmaf( yA.y, tw.x, acc[0].y));
        acc[1].x = fmaf(yA.z, tw.x, fmaf(-yA.w, tw.y, acc[1].x));
        acc[1].y = fmaf(yA.z, tw.y, fmaf( yA.w, tw.x, acc[1].y));
        acc[2].x = fmaf(yB.x, tw.x, fmaf(-yB.y, tw.y, acc[2].x));
        acc[2].y = fmaf(yB.x, tw.y, fmaf( yB.y, tw.x, acc[2].y));
        acc[3].x = fmaf(yB.z, tw.x, fmaf(-yB.w, tw.y, acc[3].x));
        acc[3].y = fmaf(yB.z, tw.y, fmaf( yB.w, tw.x, acc[3].y));
    }
#pragma unroll
    for (int j = 0; j < 4; j++)
        g_Y[(rowBase + rg * 4 + j) * M2 + ky] = acc[j];
}

// ---------------- Stage B: complex DFT along H (128 -> 64), radix-4, ky-pair via LDS.128 ----------------
__global__ __launch_bounds__(256) void kB() {
    __shared__ __align__(16) float2 ys[4][32][32];   // [cls][n1][ky] 32 KB
    __shared__ float2 tws[SS][33];                   // [s][n1] ~16.9 KB
    int tid = threadIdx.x;
    int bi  = blockIdx.x;
    const float2* Yg = g_Y + (size_t)bi * HH * M2;

    for (int idx = tid; idx < SS * 32; idx += 256) {
        int s = idx >> 5, n1 = idx & 31;
        tws[s][n1] = g_FB[idx];
    }

#pragma unroll
    for (int it = 0; it < 4; it++) {
        int idx = tid + 256 * it;
        int n1 = idx >> 5, ky = idx & 31;
        float2 Y0 = Yg[n1 * 32 + ky];
        float2 Y1 = Yg[(n1 + 32) * 32 + ky];
        float2 Y2 = Yg[(n1 + 64) * 32 + ky];
        float2 Y3 = Yg[(n1 + 96) * 32 + ky];
        float2 a = make_float2(Y0.x + Y2.x, Y0.y + Y2.y);
        float2 b = make_float2(Y0.x - Y2.x, Y0.y - Y2.y);
        float2 c = make_float2(Y1.x + Y3.x, Y1.y + Y3.y);
        float2 d = make_float2(Y1.x - Y3.x, Y1.y - Y3.y);
        ys[0][n1][ky] = make_float2(a.x + c.x, a.y + c.y);
        ys[2][n1][ky] = make_float2(a.x - c.x, a.y - c.y);
        ys[1][n1][ky] = make_float2(b.x + d.y, b.y - d.x);
        ys[3][n1][ky] = make_float2(b.x - d.y, b.y + d.x);
    }
    __syncthreads();

    int kh = tid & 15, sg = tid >> 4;
    int ky0 = 2 * kh, ky1 = ky0 + 1;
    int cls = sg & 3;
    float2 a0[4], a1[4];
#pragma unroll
    for (int j = 0; j < 4; j++) { a0[j] = make_float2(0.f, 0.f); a1[j] = make_float2(0.f, 0.f); }

    for (int n1 = 0; n1 < 32; n1++) {
        float4 yq = *(const float4*)&ys[cls][n1][ky0];
#pragma unroll
        for (int j = 0; j < 4; j++) {
            float2 tw = tws[sg + 16 * j][n1];
            a0[j].x = fmaf(yq.x, tw.x, fmaf(-yq.y, tw.y, a0[j].x));
            a0[j].y = fmaf(yq.x, tw.y, fmaf( yq.y, tw.x, a0[j].y));
            a1[j].x = fmaf(yq.z, tw.x, fmaf(-yq.w, tw.y, a1[j].x));
            a1[j].y = fmaf(yq.z, tw.y, fmaf( yq.w, tw.x, a1[j].y));
        }
    }
#pragma unroll
    for (int j = 0; j < 4; j++) {
        int s = sg + 16 * j;
        g_X[((size_t)(s * 32 + ky0)) * (BB * CI) + bi] = a0[j];
        g_X[((size_t)(s * 32 + ky1)) * (BB * CI) + bi] = a1[j];
    }
}

// ---------------- Stage C: per-mode channel mix G = X * conj(W) ----------------
__global__ __launch_bounds__(128, 7) void kC() {
    __shared__ float2 Xs[BB][32];   // [b][i_local] 8 KB
    __shared__ float2 Ws[32][CO];   // [i_local][o] 16 KB
    int tid  = threadIdx.x;
    int mode = blockIdx.x;

    const float2* Xg = g_X + (size_t)mode * (BB * CI);
    const float2* Wg = g_W + (size_t)mode * (CI * CO);

    int o = tid & 31, bg = tid >> 5;
    float2 acc[16];
#pragma unroll
    for (int k = 0; k < 16; k++) acc[k] = make_float2(0.f, 0.f);

    for (int c = 0; c < 2; c++) {
        __syncthreads();
        for (int idx = tid; idx < BB * 32; idx += 128) {
            int b = idx >> 5, il = idx & 31;
            Xs[b][il] = Xg[b * CI + c * 32 + il];
        }
        for (int idx = tid; idx < 32 * CO; idx += 128)
            ((float2*)Ws)[idx] = Wg[c * 32 * CO + idx];
        __syncthreads();

        for (int il = 0; il < 32; il++) {
            float2 w0 = Ws[il][o];
            float2 w1 = Ws[il][o + 32];
#pragma unroll
            for (int k = 0; k < 8; k++) {
                float2 xv = Xs[bg + 4 * k][il];
                acc[k].x      = fmaf(xv.x, w0.x, fmaf( xv.y, w0.y, acc[k].x));
                acc[k].y      = fmaf(xv.y, w0.x, fmaf(-xv.x, w0.y, acc[k].y));
                acc[k + 8].x  = fmaf(xv.x, w1.x, fmaf( xv.y, w1.y, acc[k + 8].x));
                acc[k + 8].y  = fmaf(xv.y, w1.x, fmaf(-xv.x, w1.y, acc[k + 8].y));
            }
        }
    }
    float2* Gp = g_G + (size_t)mode * (BB * CO);
#pragma unroll
    for (int k = 0; k < 8; k++) {
        int b = bg + 4 * k;
        Gp[b * CO + o]      = acc[k];
        Gp[b * CO + o + 32] = acc[k + 8];
    }
}

// ---------------- Stage D: inverse length-65 DFT along ky, conjugate-pair folded ----------------
// T(m) and T(65-m) share products: P=ΣGr·c, Q=ΣGi·s, R=ΣGr·s, S=ΣGi·c ->
// T(m)=(P-Q, R+S), T(65-m)=(P+Q, S-R). 4 FMA/ky for TWO outputs (was 8).
// 272 threads: mh = tid%34 (m-unit 0..32 active, 33 idle), bg = tid/34 (4 bo each).
__global__ __launch_bounds__(272, 4) void kD() {
    __shared__ float2 Gs[M2][33];     // [ky][bo_local]
    __shared__ float2 Ks[M2][34];     // [ky][m 0..33]
    int tid = threadIdx.x;
    int s  = blockIdx.x >> 6;
    int cb = blockIdx.x & 63;
    int bo0 = cb * 32;

    for (int idx = tid; idx < M2 * 32; idx += 272) {
        int ky = idx >> 5, bol = idx & 31;
        Gs[ky][bol] = g_G[(size_t)(s * 32 + ky) * (BB * CO) + bo0 + bol];
    }
    for (int idx = tid; idx < M2 * 34; idx += 272) {
        int ky = idx / 34, m = idx % 34;
        Ks[ky][m] = g_IKY[ky * MPAD + m];
    }
    __syncthreads();

    int mh = tid % 34, bg = tid / 34;   // bg 0..7
    float P[4], Q[4], R[4], S[4];
#pragma unroll
    for (int j = 0; j < 4; j++) { P[j] = Q[j] = R[j] = S[j] = 0.f; }

    for (int ky = 0; ky < M2; ky++) {
        float2 e = Ks[ky][mh];
#pragma unroll
        for (int j = 0; j < 4; j++) {
            float2 g = Gs[ky][bg + 8 * j];
            P[j] = fmaf(g.x, e.x, P[j]);
            Q[j] = fmaf(g.y, e.y, Q[j]);
            R[j] = fmaf(g.x, e.y, R[j]);
            S[j] = fmaf(g.y, e.x, S[j]);
        }
    }
    if (mh < 33) {
#pragma unroll
        for (int j = 0; j < 4; j++) {
            int bo = bo0 + bg + 8 * j;
            float2* Tp = &g_T[((size_t)bo * SS + s) * MPAD];
            Tp[mh]      = make_float2(P[j] - Q[j], R[j] + S[j]);
            Tp[65 - mh] = make_float2(P[j] + Q[j], S[j] - R[j]);   // mh=0 -> dead col 65, harmless
        }
    }
}

// ---------------- Stage E: inverse DFT along kx, real-output conjugate fold + radix-4 ----------------
// U(s) = T(s) + conj(T(64-s)) for s=1..31 (in smem); out = Re(Σ_{s=0..32} U(s) e(kx(s), n)).
// Classes r = kx&3: A0/A2 real-only, A1/A3 complex; s=0 term (e=1) added in epilogue.
// 272 threads: mh = tid%34 -> m pair {2mh,2mh+1}; ng = tid/34 -> n1 = ng + 8jn.
__global__ __launch_bounds__(272) void kE(float* __restrict__ out) {
    __shared__ __align__(16) float2 Tf[64][MPAD];   // full T: 34.8 KB (becomes U in rows 1..31)
    __shared__ __align__(16) float2 EsT[33][32];    // [s][col], col = (n1&7)*4 + (n1>>3): 8.4 KB
    int tid = threadIdx.x;
    int bo  = blockIdx.x;
    int mh = tid % 34, ng = tid / 34;
    int m0 = 2 * mh, m1 = m0 + 1;

    const float2* Tg = g_T + (size_t)bo * SS * MPAD;
    for (int idx = tid; idx < 64 * MPAD; idx += 272)
        ((float2*)Tf)[idx] = Tg[idx];
    for (int idx = tid; idx < 33 * 32; idx += 272) {
        int sR = idx >> 5, n1 = idx & 31;
        EsT[sR][(n1 & 7) * 4 + (n1 >> 3)] = g_E2[sR * 32 + n1];
    }
    __syncthreads();

    // U fold in place: rows 1..31 (read rows 33..63 only — disjoint)
    for (int idx = tid; idx < 31 * MPAD; idx += 272) {
        int sU = 1 + idx / MPAD, m = idx % MPAD;
        float2 a = Tf[sU][m], b = Tf[64 - sU][m];
        Tf[sU][m] = make_float2(a.x + b.x, a.y - b.y);
    }
    __syncthreads();

    float2 A0[4], A2[4], A1r[4], A1i[4], A3r[4], A3i[4];
#pragma unroll
    for (int j = 0; j < 4; j++) {
        A0[j] = A2[j] = make_float2(0.f, 0.f);
        A1r[j] = A1i[j] = A3r[j] = A3i[j] = make_float2(0.f, 0.f);
    }

    int c0 = ng * 4;
    for (int u = 0; u < 8; u++) {
        // ---- cls1: s = 4u+1 (complex accumulate) ----
        {
            int s = 4 * u + 1;
            float4 tq = *(const float4*)&Tf[s][m0];
            float4 eA = *(const float4*)&EsT[s][c0];
            float4 eB = *(const float4*)&EsT[s][c0 + 2];
            float2 ev[4] = { make_float2(eA.x, eA.y), make_float2(eA.z, eA.w),
                             make_float2(eB.x, eB.y), make_float2(eB.z, eB.w) };
#pragma unroll
            for (int jn = 0; jn < 4; jn++) {
                float2 e = ev[jn];
                A1r[jn].x = fmaf(tq.x, e.x, fmaf(-tq.y, e.y, A1r[jn].x));
                A1r[jn].y = fmaf(tq.z, e.x, fmaf(-tq.w, e.y, A1r[jn].y));
                A1i[jn].x = fmaf(tq.x, e.y, fmaf( tq.y, e.x, A1i[jn].x));
                A1i[jn].y = fmaf(tq.z, e.y, fmaf( tq.w, e.x, A1i[jn].y));
            }
        }
        // ---- cls2: s = 4u+2 (real part only) ----
        {
            int s = 4 * u + 2;
            float4 tq = *(const float4*)&Tf[s][m0];
            float4 eA = *(const float4*)&EsT[s][c0];
            float4 eB = *(const float4*)&EsT[s][c0 + 2];
            float2 ev[4] = { make_float2(eA.x, eA.y), make_float2(eA.z, eA.w),
                             make_float2(eB.x, eB.y), make_float2(eB.z, eB.w) };
#pragma unroll
            for (int jn = 0; jn < 4; jn++) {
                float2 e = ev[jn];
                A2[jn].x = fmaf(tq.x, e.x, fmaf(-tq.y, e.y, A2[jn].x));
                A2[jn].y = fmaf(tq.z, e.x, fmaf(-tq.w, e.y, A2[jn].y));
            }
        }
        // ---- cls3: s = 4u+3 (complex accumulate) ----
        {
            int s = 4 * u + 3;
            float4 tq = *(const float4*)&Tf[s][m0];
            float4 eA = *(const float4*)&EsT[s][c0];
            float4 eB = *(const float4*)&EsT[s][c0 + 2];
            float2 ev[4] = { make_float2(eA.x, eA.y), make_float2(eA.z, eA.w),
                             make_float2(eB.x, eB.y), make_float2(eB.z, eB.w) };
#pragma unroll
            for (int jn = 0; jn < 4; jn++) {
                float2 e = ev[jn];
                A3r[jn].x = fmaf(tq.x, e.x, fmaf(-tq.y, e.y, A3r[jn].x));
                A3r[jn].y = fmaf(tq.z, e.x, fmaf(-tq.w, e.y, A3r[jn].y));
                A3i[jn].x = fmaf(tq.x, e.y, fmaf( tq.y, e.x, A3i[jn].x));
                A3i[jn].y = fmaf(tq.z, e.y, fmaf( tq.w, e.x, A3i[jn].y));
            }
        }
        // ---- cls0: s = 4u+4 (real part only; u=7 -> s=32 = kx 96) ----
        {
            int s = 4 * u + 4;
            float4 tq = *(const float4*)&Tf[s][m0];
            float4 eA = *(const float4*)&EsT[s][c0];
            float4 eB = *(const float4*)&EsT[s][c0 + 2];
            float2 ev[4] = { make_float2(eA.x, eA.y), make_float2(eA.z, eA.w),
                             make_float2(eB.x, eB.y), make_float2(eB.z, eB.w) };
#pragma unroll
            for (int jn = 0; jn < 4; jn++) {
                float2 e = ev[jn];
                A0[jn].x = fmaf(tq.x, e.x, fmaf(-tq.y, e.y, A0[jn].x));
                A0[jn].y = fmaf(tq.z, e.x, fmaf(-tq.w, e.y, A0[jn].y));
            }
        }
    }

    // s = 0 term: e == 1 -> add Re(T(0)) to A0 for all n1
    {
        float4 t0 = *(const float4*)&Tf[0][m0];
#pragma unroll
        for (int jn = 0; jn < 4; jn++) { A0[jn].x += t0.x; A0[jn].y += t0.z; }
    }

    float* op = out + (size_t)bo * HH * WOUT;
    const float sc = 1.0f / (128.0f * 65.0f);
#pragma unroll
    for (int jn = 0; jn < 4; jn++) {
        int n1 = ng + 8 * jn;
        float a0m0 = A0[jn].x, a1m0 = A1r[jn].x, a2m0 = A2[jn].x, a3m0 = A3r[jn].x;
        float b1m0 = A1i[jn].x, b3m0 = A3i[jn].x;
        float a0m1 = A0[jn].y, a1m1 = A1r[jn].y, a2m1 = A2[jn].y, a3m1 = A3r[jn].y;
        float b1m1 = A1i[jn].y, b3m1 = A3i[jn].y;
        if (m0 < WOUT) {
            op[(size_t)(n1      ) * WOUT + m0] = (a0m0 + a1m0 + a2m0 + a3m0) * sc;
            op[(size_t)(n1 + 32 ) * WOUT + m0] = (a0m0 - b1m0 - a2m0 + b3m0) * sc;
            op[(size_t)(n1 + 64 ) * WOUT + m0] = (a0m0 - a1m0 + a2m0 - a3m0) * sc;
            op[(size_t)(n1 + 96 ) * WOUT + m0] = (a0m0 + b1m0 - a2m0 - b3m0) * sc;
        }
        if (m1 < WOUT) {
            op[(size_t)(n1      ) * WOUT + m1] = (a0m1 + a1m1 + a2m1 + a3m1) * sc;
            op[(size_t)(n1 + 32 ) * WOUT + m1] = (a0m1 - b1m1 - a2m1 + b3m1) * sc;
            op[(size_t)(n1 + 64 ) * WOUT + m1] = (a0m1 - a1m1 + a2m1 - a3m1) * sc;
            op[(size_t)(n1 + 96 ) * WOUT + m1] = (a0m1 + b1m1 - a2m1 - b3m1) * sc;
        }
    }
}

// ---------------- launch ----------------
extern "C" void kernel_launch(void* const* d_in, const int* in_sizes, int n_in,
                              void* d_out, int out_size) {
    (void)in_sizes; (void)n_in; (void)out_size;
    const float* x   = (const float*)d_in[0];
    const float* w1r = (const float*)d_in[1];
    const float* w1i = (const float*)d_in[2];
    const float* w2r = (const float*)d_in[3];
    const float* w2i = (const float*)d_in[4];
    float* out = (float*)d_out;

    k_fill<<<32, 256>>>();
    kW<<<SS * CI, 256>>>(w1r, w1i, w2r, w2i);        // 4096 blocks
    kA<<<(BB * CI * HH) / 32, 256>>>(x);            // 8192 blocks
    kB<<<BB * CI, 256>>>();                          // 2048 blocks
    kC<<<SS * M2, 128>>>();                          // 2048 blocks
    kD<<<SS * 64, 272>>>();                          // 4096 blocks
    kE<<<BB * CO, 272>>>(out);                       // 2048 blocks
}

// round 12
// speedup vs baseline: 1.7301x; 1.1139x over previous
#include <cuda_runtime.h>

// Problem constants
#define BB   32
#define CI   64
#define CO   64
#define HH   128
#define WW   128
#define M1   32
#define M2   32
#define SS   64      // retained kx rows: {0..31} U {96..127}
#define WOUT 65      // rfft width = W/2+1 = ifft length on last axis
#define MPAD 68      // m padded for tiling

// ---------------- scratch (device globals) ----------------
__device__ float2 g_Y[(size_t)BB * CI * HH * M2];    // stage A out: [bi][n][ky]
__device__ float2 g_X[(size_t)SS * M2 * BB * CI];    // stage B out: [mode][b*64+i]
__device__ float2 g_G[(size_t)SS * M2 * BB * CO];    // stage C out: [mode][b*64+o]
__device__ float2 g_T[(size_t)BB * CO * SS * MPAD];  // stage D out: [bo][s][m]
__device__ float2 g_W[(size_t)SS * M2 * CI * CO];    // transposed weights: [mode][i][o]

// twiddle tables (radix-8: n1 < 16)
__device__ float2 g_FA[16 * M2];     // [n1][ky]  e^{-2pi i ky n1/128}
__device__ float2 g_FB[SS * 16];     // [s][n1]   e^{-2pi i kx(s) n1/128}
__device__ float2 g_E2[SS * 32];     // [s][n1]   e^{+2pi i kx(s) n1/128}
__device__ float2 g_IKY[M2 * MPAD];  // [ky][m]   e^{+2pi i ky m/65}

// ---------------- twiddle fill ----------------
__global__ void k_fill() {
    int t  = blockIdx.x * blockDim.x + threadIdx.x;
    int NT = gridDim.x * blockDim.x;
    const double P2 = 6.283185307179586476925286766559;

    for (int idx = t; idx < 16 * M2; idx += NT) {
        int n1 = idx >> 5, ky = idx & 31;
        double a = -P2 * (double)((ky * n1) & 127) / 128.0;
        g_FA[idx] = make_float2((float)cos(a), (float)sin(a));
    }
    for (int idx = t; idx < SS * 16; idx += NT) {
        int s = idx >> 4, n1 = idx & 15;
        int kx = (s < 32) ? s : (s + 64);
        double a = -P2 * (double)((kx * n1) & 127) / 128.0;
        g_FB[idx] = make_float2((float)cos(a), (float)sin(a));
    }
    for (int idx = t; idx < SS * 32; idx += NT) {
        int s = idx >> 5, n1 = idx & 31;
        int kx = (s < 32) ? s : (s + 64);
        double a = P2 * (double)((kx * n1) & 127) / 128.0;
        g_E2[idx] = make_float2((float)cos(a), (float)sin(a));
    }
    for (int idx = t; idx < M2 * MPAD; idx += NT) {
        int ky = idx / MPAD, m = idx % MPAD;
        double a = P2 * (double)((ky * m) % 65) / 65.0;
        g_IKY[idx] = make_float2((float)cos(a), (float)sin(a));
    }
}

// ---------------- kW: weight transpose -> g_W[mode][i][o] ----------------
__global__ __launch_bounds__(256) void kW(const float* __restrict__ w1r, const float* __restrict__ w1i,
                                          const float* __restrict__ w2r, const float* __restrict__ w2i) {
    __shared__ float2 tile[CO][33];
    int tid = threadIdx.x;
    int s = blockIdx.x >> 6, i = blockIdx.x & 63;
    const float* wr = (s < 32) ? w1r : w2r;
    const float* wi = (s < 32) ? w1i : w2i;
    int sm = s & 31;

    for (int idx = tid; idx < CO * M2; idx += 256) {
        int o = idx >> 5, ky = idx & 31;
        size_t g = ((size_t)(i * CO + o) * M1 + sm) * M2 + ky;
        tile[o][ky] = make_float2(wr[g], wi[g]);
    }
    __syncthreads();
    for (int idx = tid; idx < M2 * CO; idx += 256) {
        int ky = idx >> 6, o = idx & 63;
        g_W[((size_t)(s * 32 + ky) * CI + i) * CO + o] = tile[o][ky];
    }
}

// ---------------- Stage A: real DFT along W (128 -> 32), RADIX-8 folded ----------------
// n = n1 + 16*n2. y_r[n1] = 8-pt DFT of x[n1+16n2] at freq r; class r = ky & 7.
// Block: 32 rows, 256 threads: ky = tid&31, rg = tid>>5 -> rows rg*4..rg*4+3.
#define KA_CSTRIDE (16 * 34 + 2)   // 546 float2; cls stride 4368B = 16B-aligned
__global__ __launch_bounds__(256, 5) void kA(const float* __restrict__ x) {
    __shared__ __align__(16) float2 ys[8][KA_CSTRIDE];   // ~34.9 KB
    __shared__ float2 tws[16][32];                       // [n1][ky] 4 KB
    int tid = threadIdx.x;

    for (int idx = tid; idx < 16 * 32; idx += 256)
        ((float2*)tws)[idx] = g_FA[idx];

    size_t rowBase = (size_t)blockIdx.x * 32;
    const float C_ = 0.70710678118654752440f;
#pragma unroll
    for (int it = 0; it < 2; it++) {
        int idx = tid + 256 * it;
        int row = idx >> 4, n1 = idx & 15;   // 32 rows x 16 n1 = 512 points
        const float* xp = x + (rowBase + row) * WW + n1;
        // even n2 (0,2,4,6) and odd n2 (1,3,5,7)
        float e0 = xp[0],  e1 = xp[32], e2 = xp[64], e3 = xp[96];
        float o0 = xp[16], o1 = xp[48], o2 = xp[80], o3 = xp[112];
        float p = e0 + e2, q = e0 - e2, u = e1 + e3, v = e3 - e1;
        float P = o0 + o2, Q = o0 - o2, U = o1 + o3, V = o3 - o1;
        float E0 = p + u, E2 = p - u;          // E1 = (q, v)
        float O0 = P + U, O2 = P - U;          // O1 = (Q, V)
        float t1x = C_ * (Q + V), t1y = C_ * (V - Q);   // t1 = c(1-i)*O1
        int base = n1 * 34 + row;
        ys[0][base] = make_float2(E0 + O0, 0.f);
        ys[4][base] = make_float2(E0 - O0, 0.f);
        ys[2][base] = make_float2(E2, -O2);             // E2 - i*O2
        ys[6][base] = make_float2(E2,  O2);
        ys[1][base] = make_float2(q + t1x,  v + t1y);   // E1 + t1
        ys[5][base] = make_float2(q - t1x,  v - t1y);   // E1 - t1
        ys[3][base] = make_float2(q - t1x,  t1y - v);   // conj(y5)
        ys[7][base] = make_float2(q + t1x, -v - t1y);   // conj(y1)
    }
    __syncthreads();

    int ky = tid & 31, rg = tid >> 5;
    int cls = ky & 7;
    float2 acc[4];
#pragma unroll
    for (int j = 0; j < 4; j++) acc[j] = make_float2(0.f, 0.f);

    for (int n1 = 0; n1 < 16; n1++) {
        float2 tw = tws[n1][ky];
        const float4* yp = (const float4*)&ys[cls][n1 * 34 + rg * 4];
        float4 yA = yp[0], yB = yp[1];   // rows rg*4+0,1 and rg*4+2,3
        acc[0].x = fmaf(yA.x, tw.x, fmaf(-yA.y, tw.y, acc[0].x));
        acc[0].y = fmaf(yA.x, tw.y, fmaf( yA.y, tw.x, acc[0].y));
        acc[1].x = fmaf(yA.z, tw.x, fmaf(-yA.w, tw.y, acc[1].x));
        acc[1].y = fmaf(yA.z, tw.y, fmaf( yA.w, tw.x, acc[1].y));
        acc[2].x = fmaf(yB.x, tw.x, fmaf(-yB.y, tw.y, acc[2].x));
        acc[2].y = fmaf(yB.x, tw.y, fmaf( yB.y, tw.x, acc[2].y));
        acc[3].x = fmaf(yB.z, tw.x, fmaf(-yB.w, tw.y, acc[3].x));
        acc[3].y = fmaf(yB.z, tw.y, fmaf( yB.w, tw.x, acc[3].y));
    }
#pragma unroll
    for (int j = 0; j < 4; j++)
        g_Y[(rowBase + rg * 4 + j) * M2 + ky] = acc[j];
}

// ---------------- Stage B: complex DFT along H (128 -> 64), RADIX-8, ky-pair via LDS.128 ----------------
// Class r = kx mod 8 = s & 7 = sg & 7 (s = sg + 16j, 16 == 0 mod 8).
__global__ __launch_bounds__(256, 5) void kB() {
    __shared__ __align__(16) float2 ys[8][16][32];   // [cls][n1][ky] 32 KB, ky contiguous
    __shared__ float2 tws[SS][17];                   // [s][n1] 8.7 KB
    int tid = threadIdx.x;
    int bi  = blockIdx.x;
    const float2* Yg = g_Y + (size_t)bi * HH * M2;

    for (int idx = tid; idx < SS * 16; idx += 256) {
        int s = idx >> 4, n1 = idx & 15;
        tws[s][n1] = g_FB[idx];
    }

    const float C_ = 0.70710678118654752440f;
#pragma unroll
    for (int it = 0; it < 2; it++) {
        int idx = tid + 256 * it;
        int n1 = idx >> 5, ky = idx & 31;   // 16 n1 x 32 ky = 512 points
        float2 ue0 = Yg[(n1      ) * 32 + ky];
        float2 ue1 = Yg[(n1 + 32 ) * 32 + ky];
        float2 ue2 = Yg[(n1 + 64 ) * 32 + ky];
        float2 ue3 = Yg[(n1 + 96 ) * 32 + ky];
        float2 uo0 = Yg[(n1 + 16 ) * 32 + ky];
        float2 uo1 = Yg[(n1 + 48 ) * 32 + ky];
        float2 uo2 = Yg[(n1 + 80 ) * 32 + ky];
        float2 uo3 = Yg[(n1 + 112) * 32 + ky];
        // even 4-pt
        float2 pe = make_float2(ue0.x + ue2.x, ue0.y + ue2.y);
        float2 qe = make_float2(ue0.x - ue2.x, ue0.y - ue2.y);
        float2 se = make_float2(ue1.x + ue3.x, ue1.y + ue3.y);
        float2 ve = make_float2(ue3.x - ue1.x, ue3.y - ue1.y);
        float2 E0 = make_float2(pe.x + se.x, pe.y + se.y);
        float2 E2 = make_float2(pe.x - se.x, pe.y - se.y);
        float2 E1 = make_float2(qe.x - ve.y, qe.y + ve.x);   // qe + i*ve
        float2 E3 = make_float2(qe.x + ve.y, qe.y - ve.x);   // qe - i*ve
        // odd 4-pt
        float2 po = make_float2(uo0.x + uo2.x, uo0.y + uo2.y);
        float2 qo = make_float2(uo0.x - uo2.x, uo0.y - uo2.y);
        float2 so = make_float2(uo1.x + uo3.x, uo1.y + uo3.y);
        float2 vo = make_float2(uo3.x - uo1.x, uo3.y - uo1.y);
        float2 O0 = make_float2(po.x + so.x, po.y + so.y);
        float2 O2 = make_float2(po.x - so.x, po.y - so.y);
        float2 O1 = make_float2(qo.x - vo.y, qo.y + vo.x);
        float2 O3 = make_float2(qo.x + vo.y, qo.y - vo.x);
        // twiddled odd terms
        float2 t1 = make_float2(C_ * (O1.x + O1.y), C_ * (O1.y - O1.x));   // c(1-i)*O1
        float2 t3 = make_float2(C_ * (O3.x - O3.y), C_ * (O3.x + O3.y));   // c(1+i)*O3
        ys[0][n1][ky] = make_float2(E0.x + O0.x, E0.y + O0.y);
        ys[4][n1][ky] = make_float2(E0.x - O0.x, E0.y - O0.y);
        ys[2][n1][ky] = make_float2(E2.x + O2.y, E2.y - O2.x);   // E2 - i*O2
        ys[6][n1][ky] = make_float2(E2.x - O2.y, E2.y + O2.x);   // E2 + i*O2
        ys[1][n1][ky] = make_float2(E1.x + t1.x, E1.y + t1.y);
        ys[5][n1][ky] = make_float2(E1.x - t1.x, E1.y - t1.y);
        ys[3][n1][ky] = make_float2(E3.x - t3.x, E3.y - t3.y);
        ys[7][n1][ky] = make_float2(E3.x + t3.x, E3.y + t3.y);
    }
    __syncthreads();

    int kh = tid & 15, sg = tid >> 4;
    int ky0 = 2 * kh, ky1 = ky0 + 1;
    int cls = sg & 7;
    float2 a0[4], a1[4];
#pragma unroll
    for (int j = 0; j < 4; j++) { a0[j] = make_float2(0.f, 0.f); a1[j] = make_float2(0.f, 0.f); }

    for (int n1 = 0; n1 < 16; n1++) {
        float4 yq = *(const float4*)&ys[cls][n1][ky0];   // y(ky0)=(x,y), y(ky1)=(z,w)
#pragma unroll
        for (int j = 0; j < 4; j++) {
            float2 tw = tws[sg + 16 * j][n1];
            a0[j].x = fmaf(yq.x, tw.x, fmaf(-yq.y, tw.y, a0[j].x));
            a0[j].y = fmaf(yq.x, tw.y, fmaf( yq.y, tw.x, a0[j].y));
            a1[j].x = fmaf(yq.z, tw.x, fmaf(-yq.w, tw.y, a1[j].x));
            a1[j].y = fmaf(yq.z, tw.y, fmaf( yq.w, tw.x, a1[j].y));
        }
    }
#pragma unroll
    for (int j = 0; j < 4; j++) {
        int s = sg + 16 * j;
        g_X[((size_t)(s * 32 + ky0)) * (BB * CI) + bi] = a0[j];
        g_X[((size_t)(s * 32 + ky1)) * (BB * CI) + bi] = a1[j];
    }
}

// ---------------- Stage C: per-mode channel mix G = X * conj(W) ----------------
__global__ __launch_bounds__(128, 7) void kC() {
    __shared__ float2 Xs[BB][32];   // [b][i_local] 8 KB
    __shared__ float2 Ws[32][CO];   // [i_local][o] 16 KB
    int tid  = threadIdx.x;
    int mode = blockIdx.x;

    const float2* Xg = g_X + (size_t)mode * (BB * CI);
    const float2* Wg = g_W + (size_t)mode * (CI * CO);

    int o = tid & 31, bg = tid >> 5;
    float2 acc[16];
#pragma unroll
    for (int k = 0; k < 16; k++) acc[k] = make_float2(0.f, 0.f);

    for (int c = 0; c < 2; c++) {
        __syncthreads();
        for (int idx = tid; idx < BB * 32; idx += 128) {
            int b = idx >> 5, il = idx & 31;
            Xs[b][il] = Xg[b * CI + c * 32 + il];
        }
        for (int idx = tid; idx < 32 * CO; idx += 128)
            ((float2*)Ws)[idx] = Wg[c * 32 * CO + idx];
        __syncthreads();

        for (int il = 0; il < 32; il++) {
            float2 w0 = Ws[il][o];
            float2 w1 = Ws[il][o + 32];
#pragma unroll
            for (int k = 0; k < 8; k++) {
                float2 xv = Xs[bg + 4 * k][il];
                acc[k].x      = fmaf(xv.x, w0.x, fmaf( xv.y, w0.y, acc[k].x));
                acc[k].y      = fmaf(xv.y, w0.x, fmaf(-xv.x, w0.y, acc[k].y));
                acc[k + 8].x  = fmaf(xv.x, w1.x, fmaf( xv.y, w1.y, acc[k + 8].x));
                acc[k + 8].y  = fmaf(xv.y, w1.x, fmaf(-xv.x, w1.y, acc[k + 8].y));
            }
        }
    }
    float2* Gp = g_G + (size_t)mode * (BB * CO);
#pragma unroll
    for (int k = 0; k < 8; k++) {
        int b = bg + 4 * k;
        Gp[b * CO + o]      = acc[k];
        Gp[b * CO + o + 32] = acc[k + 8];
    }
}

// ---------------- Stage D: inverse length-65 DFT along ky, conjugate-pair folded ----------------
__global__ __launch_bounds__(272, 4) void kD() {
    __shared__ float2 Gs[M2][33];     // [ky][bo_local]
    __shared__ float2 Ks[M2][34];     // [ky][m 0..33]
    int tid = threadIdx.x;
    int s  = blockIdx.x >> 6;
    int cb = blockIdx.x & 63;
    int bo0 = cb * 32;

    for (int idx = tid; idx < M2 * 32; idx += 272) {
        int ky = idx >> 5, bol = idx & 31;
        Gs[ky][bol] = g_G[(size_t)(s * 32 + ky) * (BB * CO) + bo0 + bol];
    }
    for (int idx = tid; idx < M2 * 34; idx += 272) {
        int ky = idx / 34, m = idx % 34;
        Ks[ky][m] = g_IKY[ky * MPAD + m];
    }
    __syncthreads();

    int mh = tid % 34, bg = tid / 34;   // bg 0..7
    float P[4], Q[4], R[4], S[4];
#pragma unroll
    for (int j = 0; j < 4; j++) { P[j] = Q[j] = R[j] = S[j] = 0.f; }

    for (int ky = 0; ky < M2; ky++) {
        float2 e = Ks[ky][mh];
#pragma unroll
        for (int j = 0; j < 4; j++) {
            float2 g = Gs[ky][bg + 8 * j];
            P[j] = fmaf(g.x, e.x, P[j]);
            Q[j] = fmaf(g.y, e.y, Q[j]);
            R[j] = fmaf(g.x, e.y, R[j]);
            S[j] = fmaf(g.y, e.x, S[j]);
        }
    }
    if (mh < 33) {
#pragma unroll
        for (int j = 0; j < 4; j++) {
            int bo = bo0 + bg + 8 * j;
            float2* Tp = &g_T[((size_t)bo * SS + s) * MPAD];
            Tp[mh]      = make_float2(P[j] - Q[j], R[j] + S[j]);
            Tp[65 - mh] = make_float2(P[j] + Q[j], S[j] - R[j]);   // mh=0 -> dead col 65, harmless
        }
    }
}

// ---------------- Stage E: inverse DFT along kx, real-output conjugate fold + radix-4 ----------------
__global__ __launch_bounds__(272) void kE(float* __restrict__ out) {
    __shared__ __align__(16) float2 Tf[64][MPAD];   // full T: 34.8 KB (becomes U in rows 1..31)
    __shared__ __align__(16) float2 EsT[33][32];    // [s][col], col = (n1&7)*4 + (n1>>3)
    int tid = threadIdx.x;
    int bo  = blockIdx.x;
    int mh = tid % 34, ng = tid / 34;
    int m0 = 2 * mh, m1 = m0 + 1;

    const float2* Tg = g_T + (size_t)bo * SS * MPAD;
    for (int idx = tid; idx < 64 * MPAD; idx += 272)
        ((float2*)Tf)[idx] = Tg[idx];
    for (int idx = tid; idx < 33 * 32; idx += 272) {
        int sR = idx >> 5, n1 = idx & 31;
        EsT[sR][(n1 & 7) * 4 + (n1 >> 3)] = g_E2[sR * 32 + n1];
    }
    __syncthreads();

    // U fold in place: rows 1..31 (read rows 33..63 only — disjoint)
    for (int idx = tid; idx < 31 * MPAD; idx += 272) {
        int sU = 1 + idx / MPAD, m = idx % MPAD;
        float2 a = Tf[sU][m], b = Tf[64 - sU][m];
        Tf[sU][m] = make_float2(a.x + b.x, a.y - b.y);
    }
    __syncthreads();

    float2 A0[4], A2[4], A1r[4], A1i[4], A3r[4], A3i[4];
#pragma unroll
    for (int j = 0; j < 4; j++) {
        A0[j] = A2[j] = make_float2(0.f, 0.f);
        A1r[j] = A1i[j] = A3r[j] = A3i[j] = make_float2(0.f, 0.f);
    }

    int c0 = ng * 4;
    for (int u = 0; u < 8; u++) {
        {
            int s = 4 * u + 1;
            float4 tq = *(const float4*)&Tf[s][m0];
            float4 eA = *(const float4*)&EsT[s][c0];
            float4 eB = *(const float4*)&EsT[s][c0 + 2];
            float2 ev[4] = { make_float2(eA.x, eA.y), make_float2(eA.z, eA.w),
                             make_float2(eB.x, eB.y), make_float2(eB.z, eB.w) };
#pragma unroll
            for (int jn = 0; jn < 4; jn++) {
                float2 e = ev[jn];
                A1r[jn].x = fmaf(tq.x, e.x, fmaf(-tq.y, e.y, A1r[jn].x));
                A1r[jn].y = fmaf(tq.z, e.x, fmaf(-tq.w, e.y, A1r[jn].y));
                A1i[jn].x = fmaf(tq.x, e.y, fmaf( tq.y, e.x, A1i[jn].x));
                A1i[jn].y = fmaf(tq.z, e.y, fmaf( tq.w, e.x, A1i[jn].y));
            }
        }
        {
            int s = 4 * u + 2;
            float4 tq = *(const float4*)&Tf[s][m0];
            float4 eA = *(const float4*)&EsT[s][c0];
            float4 eB = *(const float4*)&EsT[s][c0 + 2];
            float2 ev[4] = { make_float2(eA.x, eA.y), make_float2(eA.z, eA.w),
                             make_float2(eB.x, eB.y), make_float2(eB.z, eB.w) };
#pragma unroll
            for (int jn = 0; jn < 4; jn++) {
                float2 e = ev[jn];
                A2[jn].x = fmaf(tq.x, e.x, fmaf(-tq.y, e.y, A2[jn].x));
                A2[jn].y = fmaf(tq.z, e.x, fmaf(-tq.w, e.y, A2[jn].y));
            }
        }
        {
            int s = 4 * u + 3;
            float4 tq = *(const float4*)&Tf[s][m0];
            float4 eA = *(const float4*)&EsT[s][c0];
            float4 eB = *(const float4*)&EsT[s][c0 + 2];
            float2 ev[4] = { make_float2(eA.x, eA.y), make_float2(eA.z, eA.w),
                             make_float2(eB.x, eB.y), make_float2(eB.z, eB.w) };
#pragma unroll
            for (int jn = 0; jn < 4; jn++) {
                float2 e = ev[jn];
                A3r[jn].x = fmaf(tq.x, e.x, fmaf(-tq.y, e.y, A3r[jn].x));
                A3r[jn].y = fmaf(tq.z, e.x, fmaf(-tq.w, e.y, A3r[jn].y));
                A3i[jn].x = fmaf(tq.x, e.y, fmaf( tq.y, e.x, A3i[jn].x));
                A3i[jn].y = fmaf(tq.z, e.y, fmaf( tq.w, e.x, A3i[jn].y));
            }
        }
        {
            int s = 4 * u + 4;
            float4 tq = *(const float4*)&Tf[s][m0];
            float4 eA = *(const float4*)&EsT[s][c0];
            float4 eB = *(const float4*)&EsT[s][c0 + 2];
            float2 ev[4] = { make_float2(eA.x, eA.y), make_float2(eA.z, eA.w),
                             make_float2(eB.x, eB.y), make_float2(eB.z, eB.w) };
#pragma unroll
            for (int jn = 0; jn < 4; jn++) {
                float2 e = ev[jn];
                A0[jn].x = fmaf(tq.x, e.x, fmaf(-tq.y, e.y, A0[jn].x));
                A0[jn].y = fmaf(tq.z, e.x, fmaf(-tq.w, e.y, A0[jn].y));
            }
        }
    }

    // s = 0 term: e == 1 -> add Re(T(0))
    {
        float4 t0 = *(const float4*)&Tf[0][m0];
#pragma unroll
        for (int jn = 0; jn < 4; jn++) { A0[jn].x += t0.x; A0[jn].y += t0.z; }
    }

    float* op = out + (size_t)bo * HH * WOUT;
    const float sc = 1.0f / (128.0f * 65.0f);
#pragma unroll
    for (int jn = 0; jn < 4; jn++) {
        int n1 = ng + 8 * jn;
        float a0m0 = A0[jn].x, a1m0 = A1r[jn].x, a2m0 = A2[jn].x, a3m0 = A3r[jn].x;
        float b1m0 = A1i[jn].x, b3m0 = A3i[jn].x;
        float a0m1 = A0[jn].y, a1m1 = A1r[jn].y, a2m1 = A2[jn].y, a3m1 = A3r[jn].y;
        float b1m1 = A1i[jn].y, b3m1 = A3i[jn].y;
        if (m0 < WOUT) {
            op[(size_t)(n1      ) * WOUT + m0] = (a0m0 + a1m0 + a2m0 + a3m0) * sc;
            op[(size_t)(n1 + 32 ) * WOUT + m0] = (a0m0 - b1m0 - a2m0 + b3m0) * sc;
            op[(size_t)(n1 + 64 ) * WOUT + m0] = (a0m0 - a1m0 + a2m0 - a3m0) * sc;
            op[(size_t)(n1 + 96 ) * WOUT + m0] = (a0m0 + b1m0 - a2m0 - b3m0) * sc;
        }
        if (m1 < WOUT) {
            op[(size_t)(n1      ) * WOUT + m1] = (a0m1 + a1m1 + a2m1 + a3m1) * sc;
            op[(size_t)(n1 + 32 ) * WOUT + m1] = (a0m1 - b1m1 - a2m1 + b3m1) * sc;
            op[(size_t)(n1 + 64 ) * WOUT + m1] = (a0m1 - a1m1 + a2m1 - a3m1) * sc;
            op[(size_t)(n1 + 96 ) * WOUT + m1] = (a0m1 + b1m1 - a2m1 - b3m1) * sc;
        }
    }
}

// ---------------- launch ----------------
extern "C" void kernel_launch(void* const* d_in, const int* in_sizes, int n_in,
                              void* d_out, int out_size) {
    (void)in_sizes; (void)n_in; (void)out_size;
    const float* x   = (const float*)d_in[0];
    const float* w1r = (const float*)d_in[1];
    const float* w1i = (const float*)d_in[2];
    const float* w2r = (const float*)d_in[3];
    const float* w2i = (const float*)d_in[4];
    float* out = (float*)d_out;

    k_fill<<<32, 256>>>();
    kW<<<SS * CI, 256>>>(w1r, w1i, w2r, w2i);        // 4096 blocks
    kA<<<(BB * CI * HH) / 32, 256>>>(x);            // 8192 blocks
    kB<<<BB * CI, 256>>>();                          // 2048 blocks
    kC<<<SS * M2, 128>>>();                          // 2048 blocks
    kD<<<SS * 64, 272>>>();                          // 4096 blocks
    kE<<<BB * CO, 272>>>(out);                       // 2048 blocks
}

// round 17
// speedup vs baseline: 1.8636x; 1.0772x over previous
#include <cuda_runtime.h>

// Problem constants
#define BB   32
#define CI   64
#define CO   64
#define HH   128
#define WW   128
#define M1   32
#define M2   32
#define SS   64      // retained kx rows: {0..31} U {96..127}
#define WOUT 65      // rfft width = W/2+1 = ifft length on last axis
#define MPAD 68      // m padding in g_IKY table

// ---------------- scratch (device globals) ----------------
__device__ float2 g_Y[(size_t)BB * CI * HH * M2];    // stage A out: [bi][n][ky]
__device__ float2 g_X[(size_t)SS * M2 * BB * CI];    // stage B out: [mode][b*64+i]
__device__ float2 g_G[(size_t)SS * M2 * BB * CO];    // stage C out: [mode][b*64+o]
__device__ float2 g_W[(size_t)SS * M2 * CI * CO];    // transposed weights: [mode][i][o]

// twiddle tables (radix-8: n1 < 16)
__device__ float2 g_FA[16 * M2];     // [n1][ky]  e^{-2pi i ky n1/128}
__device__ float2 g_FB[SS * 16];     // [s][n1]   e^{-2pi i kx(s) n1/128}
__device__ float2 g_E2[SS * 32];     // [s][n1]   e^{+2pi i kx(s) n1/128}
__device__ float2 g_IKY[M2 * MPAD];  // [ky][m]   e^{+2pi i ky m/65}

// ---------------- twiddle fill ----------------
__global__ void k_fill() {
    int t  = blockIdx.x * blockDim.x + threadIdx.x;
    int NT = gridDim.x * blockDim.x;
    const double P2 = 6.283185307179586476925286766559;

    for (int idx = t; idx < 16 * M2; idx += NT) {
        int n1 = idx >> 5, ky = idx & 31;
        double a = -P2 * (double)((ky * n1) & 127) / 128.0;
        g_FA[idx] = make_float2((float)cos(a), (float)sin(a));
    }
    for (int idx = t; idx < SS * 16; idx += NT) {
        int s = idx >> 4, n1 = idx & 15;
        int kx = (s < 32) ? s : (s + 64);
        double a = -P2 * (double)((kx * n1) & 127) / 128.0;
        g_FB[idx] = make_float2((float)cos(a), (float)sin(a));
    }
    for (int idx = t; idx < SS * 32; idx += NT) {
        int s = idx >> 5, n1 = idx & 31;
        int kx = (s < 32) ? s : (s + 64);
        double a = P2 * (double)((kx * n1) & 127) / 128.0;
        g_E2[idx] = make_float2((float)cos(a), (float)sin(a));
    }
    for (int idx = t; idx < M2 * MPAD; idx += NT) {
        int ky = idx / MPAD, m = idx % MPAD;
        double a = P2 * (double)((ky * m) % 65) / 65.0;
        g_IKY[idx] = make_float2((float)cos(a), (float)sin(a));
    }
}

// ---------------- kW: weight transpose -> g_W[mode][i][o] ----------------
__global__ __launch_bounds__(256) void kW(const float* __restrict__ w1r, const float* __restrict__ w1i,
                                          const float* __restrict__ w2r, const float* __restrict__ w2i) {
    __shared__ float2 tile[CO][33];
    int tid = threadIdx.x;
    int s = blockIdx.x >> 6, i = blockIdx.x & 63;
    const float* wr = (s < 32) ? w1r : w2r;
    const float* wi = (s < 32) ? w1i : w2i;
    int sm = s & 31;

    for (int idx = tid; idx < CO * M2; idx += 256) {
        int o = idx >> 5, ky = idx & 31;
        size_t g = ((size_t)(i * CO + o) * M1 + sm) * M2 + ky;
        tile[o][ky] = make_float2(wr[g], wi[g]);
    }
    __syncthreads();
    for (int idx = tid; idx < M2 * CO; idx += 256) {
        int ky = idx >> 6, o = idx & 63;
        g_W[((size_t)(s * 32 + ky) * CI + i) * CO + o] = tile[o][ky];
    }
}

// ---------------- Stage A: real DFT along W (128 -> 32), RADIX-8 folded ----------------
#define KA_CSTRIDE (16 * 34 + 2)   // 546 float2; cls stride 4368B = 16B-aligned
__global__ __launch_bounds__(256, 5) void kA(const float* __restrict__ x) {
    __shared__ __align__(16) float2 ys[8][KA_CSTRIDE];   // ~34.9 KB
    __shared__ float2 tws[16][32];                       // [n1][ky] 4 KB
    int tid = threadIdx.x;

    for (int idx = tid; idx < 16 * 32; idx += 256)
        ((float2*)tws)[idx] = g_FA[idx];

    size_t rowBase = (size_t)blockIdx.x * 32;
    const float C_ = 0.70710678118654752440f;
#pragma unroll
    for (int it = 0; it < 2; it++) {
        int idx = tid + 256 * it;
        int row = idx >> 4, n1 = idx & 15;   // 32 rows x 16 n1 = 512 points
        const float* xp = x + (rowBase + row) * WW + n1;
        float e0 = xp[0],  e1 = xp[32], e2 = xp[64], e3 = xp[96];
        float o0 = xp[16], o1 = xp[48], o2 = xp[80], o3 = xp[112];
        float p = e0 + e2, q = e0 - e2, u = e1 + e3, v = e3 - e1;
        float P = o0 + o2, Q = o0 - o2, U = o1 + o3, V = o3 - o1;
        float E0 = p + u, E2 = p - u;
        float O0 = P + U, O2 = P - U;
        float t1x = C_ * (Q + V), t1y = C_ * (V - Q);
        int base = n1 * 34 + row;
        ys[0][base] = make_float2(E0 + O0, 0.f);
        ys[4][base] = make_float2(E0 - O0, 0.f);
        ys[2][base] = make_float2(E2, -O2);
        ys[6][base] = make_float2(E2,  O2);
        ys[1][base] = make_float2(q + t1x,  v + t1y);
        ys[5][base] = make_float2(q - t1x,  v - t1y);
        ys[3][base] = make_float2(q - t1x,  t1y - v);
        ys[7][base] = make_float2(q + t1x, -v - t1y);
    }
    __syncthreads();

    int ky = tid & 31, rg = tid >> 5;
    int cls = ky & 7;
    float2 acc[4];
#pragma unroll
    for (int j = 0; j < 4; j++) acc[j] = make_float2(0.f, 0.f);

    for (int n1 = 0; n1 < 16; n1++) {
        float2 tw = tws[n1][ky];
        const float4* yp = (const float4*)&ys[cls][n1 * 34 + rg * 4];
        float4 yA = yp[0], yB = yp[1];
        acc[0].x = fmaf(yA.x, tw.x, fmaf(-yA.y, tw.y, acc[0].x));
        acc[0].y = fmaf(yA.x, tw.y, fmaf( yA.y, tw.x, acc[0].y));
        acc[1].x = fmaf(yA.z, tw.x, fmaf(-yA.w, tw.y, acc[1].x));
        acc[1].y = fmaf(yA.z, tw.y, fmaf( yA.w, tw.x, acc[1].y));
        acc[2].x = fmaf(yB.x, tw.x, fmaf(-yB.y, tw.y, acc[2].x));
        acc[2].y = fmaf(yB.x, tw.y, fmaf( yB.y, tw.x, acc[2].y));
        acc[3].x = fmaf(yB.z, tw.x, fmaf(-yB.w, tw.y, acc[3].x));
        acc[3].y = fmaf(yB.z, tw.y, fmaf( yB.w, tw.x, acc[3].y));
    }
#pragma unroll
    for (int j = 0; j < 4; j++)
        g_Y[(rowBase + rg * 4 + j) * M2 + ky] = acc[j];
}

// ---------------- Stage B: complex DFT along H (128 -> 64), RADIX-8, ky-pair via LDS.128 ----------------
__global__ __launch_bounds__(256, 5) void kB() {
    __shared__ __align__(16) float2 ys[8][16][32];   // [cls][n1][ky] 32 KB
    __shared__ float2 tws[SS][17];                   // [s][n1] 8.7 KB
    int tid = threadIdx.x;
    int bi  = blockIdx.x;
    const float2* Yg = g_Y + (size_t)bi * HH * M2;

    for (int idx = tid; idx < SS * 16; idx += 256) {
        int s = idx >> 4, n1 = idx & 15;
        tws[s][n1] = g_FB[idx];
    }

    const float C_ = 0.70710678118654752440f;
#pragma unroll
    for (int it = 0; it < 2; it++) {
        int idx = tid + 256 * it;
        int n1 = idx >> 5, ky = idx & 31;
        float2 ue0 = Yg[(n1      ) * 32 + ky];
        float2 ue1 = Yg[(n1 + 32 ) * 32 + ky];
        float2 ue2 = Yg[(n1 + 64 ) * 32 + ky];
        float2 ue3 = Yg[(n1 + 96 ) * 32 + ky];
        float2 uo0 = Yg[(n1 + 16 ) * 32 + ky];
        float2 uo1 = Yg[(n1 + 48 ) * 32 + ky];
        float2 uo2 = Yg[(n1 + 80 ) * 32 + ky];
        float2 uo3 = Yg[(n1 + 112) * 32 + ky];
        float2 pe = make_float2(ue0.x + ue2.x, ue0.y + ue2.y);
        float2 qe = make_float2(ue0.x - ue2.x, ue0.y - ue2.y);
        float2 se = make_float2(ue1.x + ue3.x, ue1.y + ue3.y);
        float2 ve = make_float2(ue3.x - ue1.x, ue3.y - ue1.y);
        float2 E0 = make_float2(pe.x + se.x, pe.y + se.y);
        float2 E2 = make_float2(pe.x - se.x, pe.y - se.y);
        float2 E1 = make_float2(qe.x - ve.y, qe.y + ve.x);
        float2 E3 = make_float2(qe.x + ve.y, qe.y - ve.x);
        float2 po = make_float2(uo0.x + uo2.x, uo0.y + uo2.y);
        float2 qo = make_float2(uo0.x - uo2.x, uo0.y - uo2.y);
        float2 so = make_float2(uo1.x + uo3.x, uo1.y + uo3.y);
        float2 vo = make_float2(uo3.x - uo1.x, uo3.y - uo1.y);
        float2 O0 = make_float2(po.x + so.x, po.y + so.y);
        float2 O2 = make_float2(po.x - so.x, po.y - so.y);
        float2 O1 = make_float2(qo.x - vo.y, qo.y + vo.x);
        float2 O3 = make_float2(qo.x + vo.y, qo.y - vo.x);
        float2 t1 = make_float2(C_ * (O1.x + O1.y), C_ * (O1.y - O1.x));
        float2 t3 = make_float2(C_ * (O3.x - O3.y), C_ * (O3.x + O3.y));
        ys[0][n1][ky] = make_float2(E0.x + O0.x, E0.y + O0.y);
        ys[4][n1][ky] = make_float2(E0.x - O0.x, E0.y - O0.y);
        ys[2][n1][ky] = make_float2(E2.x + O2.y, E2.y - O2.x);
        ys[6][n1][ky] = make_float2(E2.x - O2.y, E2.y + O2.x);
        ys[1][n1][ky] = make_float2(E1.x + t1.x, E1.y + t1.y);
        ys[5][n1][ky] = make_float2(E1.x - t1.x, E1.y - t1.y);
        ys[3][n1][ky] = make_float2(E3.x - t3.x, E3.y - t3.y);
        ys[7][n1][ky] = make_float2(E3.x + t3.x, E3.y + t3.y);
    }
    __syncthreads();

    int kh = tid & 15, sg = tid >> 4;
    int ky0 = 2 * kh, ky1 = ky0 + 1;
    int cls = sg & 7;
    float2 a0[4], a1[4];
#pragma unroll
    for (int j = 0; j < 4; j++) { a0[j] = make_float2(0.f, 0.f); a1[j] = make_float2(0.f, 0.f); }

    for (int n1 = 0; n1 < 16; n1++) {
        float4 yq = *(const float4*)&ys[cls][n1][ky0];
#pragma unroll
        for (int j = 0; j < 4; j++) {
            float2 tw = tws[sg + 16 * j][n1];
            a0[j].x = fmaf(yq.x, tw.x, fmaf(-yq.y, tw.y, a0[j].x));
            a0[j].y = fmaf(yq.x, tw.y, fmaf( yq.y, tw.x, a0[j].y));
            a1[j].x = fmaf(yq.z, tw.x, fmaf(-yq.w, tw.y, a1[j].x));
            a1[j].y = fmaf(yq.z, tw.y, fmaf( yq.w, tw.x, a1[j].y));
        }
    }
#pragma unroll
    for (int j = 0; j < 4; j++) {
        int s = sg + 16 * j;
        g_X[((size_t)(s * 32 + ky0)) * (BB * CI) + bi] = a0[j];
        g_X[((size_t)(s * 32 + ky1)) * (BB * CI) + bi] = a1[j];
    }
}

// ---------------- Stage C: per-mode channel mix G = X * conj(W) ----------------
__global__ __launch_bounds__(128, 7) void kC() {
    __shared__ float2 Xs[BB][32];   // [b][i_local] 8 KB
    __shared__ float2 Ws[32][CO];   // [i_local][o] 16 KB
    int tid  = threadIdx.x;
    int mode = blockIdx.x;

    const float2* Xg = g_X + (size_t)mode * (BB * CI);
    const float2* Wg = g_W + (size_t)mode * (CI * CO);

    int o = tid & 31, bg = tid >> 5;
    float2 acc[16];
#pragma unroll
    for (int k = 0; k < 16; k++) acc[k] = make_float2(0.f, 0.f);

    for (int c = 0; c < 2; c++) {
        __syncthreads();
        for (int idx = tid; idx < BB * 32; idx += 128) {
            int b = idx >> 5, il = idx & 31;
            Xs[b][il] = Xg[b * CI + c * 32 + il];
        }
        for (int idx = tid; idx < 32 * CO; idx += 128)
            ((float2*)Ws)[idx] = Wg[c * 32 * CO + idx];
        __syncthreads();

        for (int il = 0; il < 32; il++) {
            float2 w0 = Ws[il][o];
            float2 w1 = Ws[il][o + 32];
#pragma unroll
            for (int k = 0; k < 8; k++) {
                float2 xv = Xs[bg + 4 * k][il];
                acc[k].x      = fmaf(xv.x, w0.x, fmaf( xv.y, w0.y, acc[k].x));
                acc[k].y      = fmaf(xv.y, w0.x, fmaf(-xv.x, w0.y, acc[k].y));
                acc[k + 8].x  = fmaf(xv.x, w1.x, fmaf( xv.y, w1.y, acc[k + 8].x));
                acc[k + 8].y  = fmaf(xv.y, w1.x, fmaf(-xv.x, w1.y, acc[k + 8].y));
            }
        }
    }
    float2* Gp = g_G + (size_t)mode * (BB * CO);
#pragma unroll
    for (int k = 0; k < 8; k++) {
        int b = bg + 4 * k;
        Gp[b * CO + o]      = acc[k];
        Gp[b * CO + o + 32] = acc[k + 8];
    }
}

// ---------------- Stage DE (fused): inverse ky-DFT (conj-pair folded) + inverse kx-DFT ----------------
// Block per bo (2048 blocks), 272 threads: mh = tid%34, sgrp = tid/34.
// D phase: 2 passes of 32 s; Gsm holds G[s-chunk][ky] for this bo (smem),
// e twiddles via L1-cached LDG from g_IKY. T built directly in smem (Tf), no g_T.
// E phase: identical to previous kE (U fold + radix-4 class accumulation).
__global__ __launch_bounds__(272) void kDE(float* __restrict__ out) {
    __shared__ __align__(16) float2 Tf[64][66];    // 33.8 KB (cols 0..65 all written by D)
    __shared__ __align__(16) float2 Buf[33 * 32];  // union: Gsm[32][32] (D) / EsT[33][32] (E)
    float2 (*Gsm)[32] = (float2(*)[32])Buf;
    float2 (*EsT)[32] = (float2(*)[32])Buf;

    int tid = threadIdx.x;
    int bo  = blockIdx.x;
    int mh = tid % 34, sgrp = tid / 34;

    // ---- D phase: two passes of 32 s each ----
#pragma unroll
    for (int pass = 0; pass < 2; pass++) {
        int S0 = pass * 32;
        __syncthreads();   // protect Buf reuse between passes (no-op cost first time)
        for (int idx = tid; idx < 1024; idx += 272) {
            int sl = idx >> 5, ky = idx & 31;
            Gsm[sl][ky] = g_G[(size_t)((S0 + sl) * 32 + ky) * (BB * CO) + bo];
        }
        __syncthreads();

        int s0 = sgrp * 4;   // local s base within chunk
        float P[4], Q[4], R[4], S[4];
#pragma unroll
        for (int j = 0; j < 4; j++) { P[j] = Q[j] = R[j] = S[j] = 0.f; }

        for (int ky = 0; ky < M2; ky++) {
            float2 e = __ldg(&g_IKY[ky * MPAD + mh]);
#pragma unroll
            for (int j = 0; j < 4; j++) {
                float2 g = Gsm[s0 + j][ky];
                P[j] = fmaf(g.x, e.x, P[j]);
                Q[j] = fmaf(g.y, e.y, Q[j]);
                R[j] = fmaf(g.x, e.y, R[j]);
                S[j] = fmaf(g.y, e.x, S[j]);
            }
        }
        if (mh < 33) {
#pragma unroll
            for (int j = 0; j < 4; j++) {
                int s = S0 + s0 + j;
                Tf[s][mh]      = make_float2(P[j] - Q[j], R[j] + S[j]);
                Tf[s][65 - mh] = make_float2(P[j] + Q[j], S[j] - R[j]);   // mh=0 -> dead col 65
            }
        }
    }
    __syncthreads();

    // ---- load EsT (Buf reuse; Gsm dead) + U fold on Tf ----
    for (int idx = tid; idx < 33 * 32; idx += 272) {
        int sR = idx >> 5, n1 = idx & 31;
        EsT[sR][(n1 & 7) * 4 + (n1 >> 3)] = g_E2[sR * 32 + n1];
    }
    // U(s) = T(s) + conj(T(64-s)), rows 1..31 in place (reads rows 33..63 — disjoint)
    for (int idx = tid; idx < 31 * 66; idx += 272) {
        int sU = 1 + idx / 66, m = idx % 66;
        float2 a = Tf[sU][m], b = Tf[64 - sU][m];
        Tf[sU][m] = make_float2(a.x + b.x, a.y - b.y);
    }
    __syncthreads();

    // ---- E phase ----
    int ng = sgrp;
    int m0 = 2 * mh, m1 = m0 + 1;
    int m0r = (mh < 33) ? m0 : 0;   // clamped read index (mh=33 outputs are discarded)

    float2 A0[4], A2[4], A1r[4], A1i[4], A3r[4], A3i[4];
#pragma unroll
    for (int j = 0; j < 4; j++) {
        A0[j] = A2[j] = make_float2(0.f, 0.f);
        A1r[j] = A1i[j] = A3r[j] = A3i[j] = make_float2(0.f, 0.f);
    }

    int c0 = ng * 4;
    for (int u = 0; u < 8; u++) {
        {
            int s = 4 * u + 1;
            float4 tq = *(const float4*)&Tf[s][m0r];
            float4 eA = *(const float4*)&EsT[s][c0];
            float4 eB = *(const float4*)&EsT[s][c0 + 2];
            float2 ev[4] = { make_float2(eA.x, eA.y), make_float2(eA.z, eA.w),
                             make_float2(eB.x, eB.y), make_float2(eB.z, eB.w) };
#pragma unroll
            for (int jn = 0; jn < 4; jn++) {
                float2 e = ev[jn];
                A1r[jn].x = fmaf(tq.x, e.x, fmaf(-tq.y, e.y, A1r[jn].x));
                A1r[jn].y = fmaf(tq.z, e.x, fmaf(-tq.w, e.y, A1r[jn].y));
                A1i[jn].x = fmaf(tq.x, e.y, fmaf( tq.y, e.x, A1i[jn].x));
                A1i[jn].y = fmaf(tq.z, e.y, fmaf( tq.w, e.x, A1i[jn].y));
            }
        }
        {
            int s = 4 * u + 2;
            float4 tq = *(const float4*)&Tf[s][m0r];
            float4 eA = *(const float4*)&EsT[s][c0];
            float4 eB = *(const float4*)&EsT[s][c0 + 2];
            float2 ev[4] = { make_float2(eA.x, eA.y), make_float2(eA.z, eA.w),
                             make_float2(eB.x, eB.y), make_float2(eB.z, eB.w) };
#pragma unroll
            for (int jn = 0; jn < 4; jn++) {
                float2 e = ev[jn];
                A2[jn].x = fmaf(tq.x, e.x, fmaf(-tq.y, e.y, A2[jn].x));
                A2[jn].y = fmaf(tq.z, e.x, fmaf(-tq.w, e.y, A2[jn].y));
            }
        }
        {
            int s = 4 * u + 3;
            float4 tq = *(const float4*)&Tf[s][m0r];
            float4 eA = *(const float4*)&EsT[s][c0];
            float4 eB = *(const float4*)&EsT[s][c0 + 2];
            float2 ev[4] = { make_float2(eA.x, eA.y), make_float2(eA.z, eA.w),
                             make_float2(eB.x, eB.y), make_float2(eB.z, eB.w) };
#pragma unroll
            for (int jn = 0; jn < 4; jn++) {
                float2 e = ev[jn];
                A3r[jn].x = fmaf(tq.x, e.x, fmaf(-tq.y, e.y, A3r[jn].x));
                A3r[jn].y = fmaf(tq.z, e.x, fmaf(-tq.w, e.y, A3r[jn].y));
                A3i[jn].x = fmaf(tq.x, e.y, fmaf( tq.y, e.x, A3i[jn].x));
                A3i[jn].y = fmaf(tq.z, e.y, fmaf( tq.w, e.x, A3i[jn].y));
            }
        }
        {
            int s = 4 * u + 4;
            float4 tq = *(const float4*)&Tf[s][m0r];
            float4 eA = *(const float4*)&EsT[s][c0];
            float4 eB = *(const float4*)&EsT[s][c0 + 2];
            float2 ev[4] = { make_float2(eA.x, eA.y), make_float2(eA.z, eA.w),
                             make_float2(eB.x, eB.y), make_float2(eB.z, eB.w) };
#pragma unroll
            for (int jn = 0; jn < 4; jn++) {
                float2 e = ev[jn];
                A0[jn].x = fmaf(tq.x, e.x, fmaf(-tq.y, e.y, A0[jn].x));
                A0[jn].y = fmaf(tq.z, e.x, fmaf(-tq.w, e.y, A0[jn].y));
            }
        }
    }

    // s = 0 term: e == 1 -> add Re(T(0))
    {
        float4 t0 = *(const float4*)&Tf[0][m0r];
#pragma unroll
        for (int jn = 0; jn < 4; jn++) { A0[jn].x += t0.x; A0[jn].y += t0.z; }
    }

    float* op = out + (size_t)bo * HH * WOUT;
    const float sc = 1.0f / (128.0f * 65.0f);
#pragma unroll
    for (int jn = 0; jn < 4; jn++) {
        int n1 = ng + 8 * jn;
        float a0m0 = A0[jn].x, a1m0 = A1r[jn].x, a2m0 = A2[jn].x, a3m0 = A3r[jn].x;
        float b1m0 = A1i[jn].x, b3m0 = A3i[jn].x;
        float a0m1 = A0[jn].y, a1m1 = A1r[jn].y, a2m1 = A2[jn].y, a3m1 = A3r[jn].y;
        float b1m1 = A1i[jn].y, b3m1 = A3i[jn].y;
        if (m0 < WOUT) {
            op[(size_t)(n1      ) * WOUT + m0] = (a0m0 + a1m0 + a2m0 + a3m0) * sc;
            op[(size_t)(n1 + 32 ) * WOUT + m0] = (a0m0 - b1m0 - a2m0 + b3m0) * sc;
            op[(size_t)(n1 + 64 ) * WOUT + m0] = (a0m0 - a1m0 + a2m0 - a3m0) * sc;
            op[(size_t)(n1 + 96 ) * WOUT + m0] = (a0m0 + b1m0 - a2m0 - b3m0) * sc;
        }
        if (m1 < WOUT) {
            op[(size_t)(n1      ) * WOUT + m1] = (a0m1 + a1m1 + a2m1 + a3m1) * sc;
            op[(size_t)(n1 + 32 ) * WOUT + m1] = (a0m1 - b1m1 - a2m1 + b3m1) * sc;
            op[(size_t)(n1 + 64 ) * WOUT + m1] = (a0m1 - a1m1 + a2m1 - a3m1) * sc;
            op[(size_t)(n1 + 96 ) * WOUT + m1] = (a0m1 + b1m1 - a2m1 - b3m1) * sc;
        }
    }
}

// ---------------- launch ----------------
extern "C" void kernel_launch(void* const* d_in, const int* in_sizes, int n_in,
                              void* d_out, int out_size) {
    (void)in_sizes; (void)n_in; (void)out_size;
    const float* x   = (const float*)d_in[0];
    const float* w1r = (const float*)d_in[1];
    const float* w1i = (const float*)d_in[2];
    const float* w2r = (const float*)d_in[3];
    const float* w2i = (const float*)d_in[4];
    float* out = (float*)d_out;

    k_fill<<<32, 256>>>();
    kW<<<SS * CI, 256>>>(w1r, w1i, w2r, w2i);        // 4096 blocks
    kA<<<(BB * CI * HH) / 32, 256>>>(x);            // 8192 blocks
    kB<<<BB * CI, 256>>>();                          // 2048 blocks
    kC<<<SS * M2, 128>>>();                          // 2048 blocks
    kDE<<<BB * CO, 272>>>(out);                      // 2048 blocks (fused D+E)
}